// round 1
// baseline (speedup 1.0000x reference)
#include <cuda_runtime.h>
#include <cuda_bf16.h>
#include <stdint.h>

#define B_   4
#define T_   256
#define U_   128
#define DE   512
#define DP   640
#define JD   1024
#define VO   1025
#define NPAD 1152   // 9 n-tiles of 128

#define KC     64
#define APITCH 72    // 64 + 8 pad (bf16 elems), pitch = 144B = 9*16B (odd granules)
#define BPITCH 136   // 128 + 8 pad, pitch = 272B = 17*16B

// ---- dynamic smem layout (bytes) ----
#define SM_ENC 0                         // float[1024]            : 4096
#define SM_AHI 4096                      // 2 x bf16[128][72]      : 2*18432
#define SM_ALO (SM_AHI + 2*18432)        // 2 x bf16[128][72]
#define SM_BHI (SM_ALO + 2*18432)        // 2 x bf16[64][136]      : 2*17408
#define SM_BLO (SM_BHI + 2*17408)
#define SM_TOTAL (SM_BLO + 2*17408)      // 147456 bytes

// ---- device scratch (allocation-free rule: __device__ globals) ----
__device__ __align__(16) float g_enc_proj[B_*T_*JD];      // 4 MB
__device__ __align__(16) float g_pred_proj[B_*U_*JD];     // 2 MB
__device__ __align__(16) __nv_bfloat16 g_Whi[JD*NPAD];    // 2.36 MB
__device__ __align__(16) __nv_bfloat16 g_Wlo[JD*NPAD];    // 2.36 MB

// =====================================================================
// helpers
// =====================================================================
__device__ __forceinline__ uint32_t smem_u32(const void* p) {
    return (uint32_t)__cvta_generic_to_shared(p);
}
__device__ __forceinline__ void ldm_x4(uint32_t* r, uint32_t addr) {
    asm volatile("ldmatrix.sync.aligned.m8n8.x4.shared.b16 {%0,%1,%2,%3}, [%4];"
                 : "=r"(r[0]), "=r"(r[1]), "=r"(r[2]), "=r"(r[3]) : "r"(addr));
}
__device__ __forceinline__ void ldm_x4_t(uint32_t* r, uint32_t addr) {
    asm volatile("ldmatrix.sync.aligned.m8n8.x4.trans.shared.b16 {%0,%1,%2,%3}, [%4];"
                 : "=r"(r[0]), "=r"(r[1]), "=r"(r[2]), "=r"(r[3]) : "r"(addr));
}
__device__ __forceinline__ void mma16816(float* c, const uint32_t* a, const uint32_t* b) {
    asm volatile(
        "mma.sync.aligned.m16n8k16.row.col.f32.bf16.bf16.f32 "
        "{%0,%1,%2,%3},{%4,%5,%6,%7},{%8,%9},{%0,%1,%2,%3};"
        : "+f"(c[0]), "+f"(c[1]), "+f"(c[2]), "+f"(c[3])
        : "r"(a[0]), "r"(a[1]), "r"(a[2]), "r"(a[3]), "r"(b[0]), "r"(b[1]));
}
__device__ __forceinline__ void cp16(void* dst_smem, const void* src) {
    uint32_t d = smem_u32(dst_smem);
    asm volatile("cp.async.cg.shared.global [%0], [%1], 16;\n" :: "r"(d), "l"(src) : "memory");
}
__device__ __forceinline__ void cp_commit() {
    asm volatile("cp.async.commit_group;\n" ::: "memory");
}
__device__ __forceinline__ void cp_wait_all() {
    asm volatile("cp.async.wait_group 0;\n" ::: "memory");
}

// =====================================================================
// kernel 1: generic fp32 projection GEMM  C[M,J] = A[M,K] @ W[K,J] + bias
// BM=BN=64, BK=16, 256 threads, 4x4 per thread
// =====================================================================
__global__ void __launch_bounds__(256) proj_gemm(
    const float* __restrict__ A, const float* __restrict__ W,
    const float* __restrict__ bias, float* __restrict__ C,
    int M, int K, int J)
{
    __shared__ float As[16][68];
    __shared__ float Bs[16][64];
    const int tx = threadIdx.x & 15;
    const int ty = threadIdx.x >> 4;
    const int m0 = blockIdx.y * 64;
    const int n0 = blockIdx.x * 64;

    float acc[4][4] = {};

    for (int k0 = 0; k0 < K; k0 += 16) {
        {
            int t = threadIdx.x;
            int m  = t >> 2, k4 = (t & 3) * 4;
            float4 a = *(const float4*)(A + (size_t)(m0 + m) * K + k0 + k4);
            As[k4 + 0][m] = a.x; As[k4 + 1][m] = a.y;
            As[k4 + 2][m] = a.z; As[k4 + 3][m] = a.w;
            int kk = t >> 4, n4 = (t & 15) * 4;
            *(float4*)&Bs[kk][n4] = *(const float4*)(W + (size_t)(k0 + kk) * J + n0 + n4);
        }
        __syncthreads();
        #pragma unroll
        for (int k = 0; k < 16; k++) {
            float a[4], b[4];
            *(float4*)a = *(float4*)&As[k][ty * 4];
            *(float4*)b = *(float4*)&Bs[k][tx * 4];
            #pragma unroll
            for (int i = 0; i < 4; i++)
                #pragma unroll
                for (int j = 0; j < 4; j++)
                    acc[i][j] += a[i] * b[j];
        }
        __syncthreads();
    }
    #pragma unroll
    for (int i = 0; i < 4; i++) {
        int m = m0 + ty * 4 + i;
        #pragma unroll
        for (int j = 0; j < 4; j++) {
            int n = n0 + tx * 4 + j;
            C[(size_t)m * J + n] = acc[i][j] + bias[n];
        }
    }
}

// =====================================================================
// kernel 2: split W_out into bf16 hi/lo, padded [JD][NPAD]
// =====================================================================
__global__ void prep_w(const float* __restrict__ W) {
    int idx = blockIdx.x * 256 + threadIdx.x;
    if (idx >= JD * NPAD) return;
    int j = idx / NPAD, n = idx % NPAD;
    float w = (n < VO) ? W[(size_t)j * VO + n] : 0.f;
    __nv_bfloat16 hi = __float2bfloat16(w);
    float lo = w - __bfloat162float(hi);
    g_Whi[idx] = hi;
    g_Wlo[idx] = __float2bfloat16(lo);
}

// =====================================================================
// kernel 3: fused joint:  out[bt,u,v] = relu(enc[bt]+pred[b,u]) @ W_out + b_out
// CTA = one (b,t) x 128 u x 128 v tile. K=1024 in 16 chunks of 64.
// bf16 split: acc += Ahi*Bhi + Ahi*Blo + Alo*Bhi
// =====================================================================
__global__ void __launch_bounds__(256, 1) joint_main(
    const float* __restrict__ bout, float* __restrict__ out)
{
    extern __shared__ char sm[];
    float* enc_s = (float*)(sm + SM_ENC);

    const int bt    = blockIdx.y;          // 0..1023
    const int b     = bt >> 8;             // T = 256
    const int ntile = blockIdx.x;          // 0..8
    const int n0    = ntile * 128;
    const int t     = threadIdx.x;
    const int warp  = t >> 5;
    const int lane  = t & 31;
    const int wm    = warp >> 2;           // 0..1 (M)
    const int wn    = warp & 3;            // 0..3 (N)
    const int lr    = lane & 15;
    const int lc    = (lane >> 4) * 8;

    const float* encg  = g_enc_proj  + (size_t)bt * JD;
    const float* predg = g_pred_proj + (size_t)b * U_ * JD;

    // enc row -> smem
    *(float4*)&enc_s[t * 4] = *(const float4*)&encg[t * 4];

    auto issueB = [&](int c, int buf) {
        const __nv_bfloat16* sHi = g_Whi + (size_t)(c * KC) * NPAD + n0;
        const __nv_bfloat16* sLo = g_Wlo + (size_t)(c * KC) * NPAD + n0;
        __nv_bfloat16* dHi = (__nv_bfloat16*)(sm + SM_BHI + buf * 17408);
        __nv_bfloat16* dLo = (__nv_bfloat16*)(sm + SM_BLO + buf * 17408);
        #pragma unroll
        for (int i = 0; i < 4; i++) {
            int flat = t + 256 * i;                 // 0..1023
            int row = flat >> 4, c16 = flat & 15;   // 64 rows x 16 x 16B
            cp16(dHi + row * BPITCH + c16 * 8, sHi + (size_t)row * NPAD + c16 * 8);
            cp16(dLo + row * BPITCH + c16 * 8, sLo + (size_t)row * NPAD + c16 * 8);
        }
        cp_commit();
    };

    auto computeA = [&](int c, int buf) {
        __nv_bfloat16* Ahi = (__nv_bfloat16*)(sm + SM_AHI + buf * 18432);
        __nv_bfloat16* Alo = (__nv_bfloat16*)(sm + SM_ALO + buf * 18432);
        const int u  = t >> 1;
        const int jh = (t & 1) * 32;
        const int j0 = c * KC + jh;
        const float4* src = (const float4*)(predg + (size_t)u * JD + j0);
        #pragma unroll
        for (int i = 0; i < 8; i++) {
            float4 p = src[i];
            float pv[4] = {p.x, p.y, p.z, p.w};
            __nv_bfloat16 hb[4], lb[4];
            #pragma unroll
            for (int jj = 0; jj < 4; jj++) {
                float h = fmaxf(pv[jj] + enc_s[j0 + i * 4 + jj], 0.f);
                __nv_bfloat16 hi = __float2bfloat16(h);
                hb[jj] = hi;
                lb[jj] = __float2bfloat16(h - __bfloat162float(hi));
            }
            int base = u * APITCH + jh + i * 4;
            *(__nv_bfloat162*)&Ahi[base + 0] = *(__nv_bfloat162*)&hb[0];
            *(__nv_bfloat162*)&Ahi[base + 2] = *(__nv_bfloat162*)&hb[2];
            *(__nv_bfloat162*)&Alo[base + 0] = *(__nv_bfloat162*)&lb[0];
            *(__nv_bfloat162*)&Alo[base + 2] = *(__nv_bfloat162*)&lb[2];
        }
    };

    float acc[4][4][4] = {};

    issueB(0, 0);
    __syncthreads();        // enc_s visible
    computeA(0, 0);

    for (int c = 0; c < 16; c++) {
        const int cur = c & 1, nxt = cur ^ 1;
        cp_wait_all();
        __syncthreads();    // A stores + B arrival visible; prev-buffer reads retired
        if (c < 15) issueB(c + 1, nxt);

        uint32_t aHiB = smem_u32(sm + SM_AHI + cur * 18432) + (uint32_t)(((wm * 64 + lr) * APITCH + lc) * 2);
        uint32_t aLoB = smem_u32(sm + SM_ALO + cur * 18432) + (uint32_t)(((wm * 64 + lr) * APITCH + lc) * 2);
        uint32_t bHiB = smem_u32(sm + SM_BHI + cur * 17408) + (uint32_t)((lr * BPITCH + wn * 32 + lc) * 2);
        uint32_t bLoB = smem_u32(sm + SM_BLO + cur * 17408) + (uint32_t)((lr * BPITCH + wn * 32 + lc) * 2);

        #pragma unroll
        for (int ks = 0; ks < 4; ks++) {
            uint32_t ah[4][4], al[4][4], bh[2][4], bl[2][4];
            #pragma unroll
            for (int mt = 0; mt < 4; mt++) {
                ldm_x4(ah[mt], aHiB + (uint32_t)((mt * 16 * APITCH + ks * 16) * 2));
                ldm_x4(al[mt], aLoB + (uint32_t)((mt * 16 * APITCH + ks * 16) * 2));
            }
            #pragma unroll
            for (int n2 = 0; n2 < 2; n2++) {
                ldm_x4_t(bh[n2], bHiB + (uint32_t)((ks * 16 * BPITCH + n2 * 16) * 2));
                ldm_x4_t(bl[n2], bLoB + (uint32_t)((ks * 16 * BPITCH + n2 * 16) * 2));
            }
            #pragma unroll
            for (int mt = 0; mt < 4; mt++)
                #pragma unroll
                for (int nt = 0; nt < 4; nt++) {
                    const uint32_t* bph = &bh[nt >> 1][(nt & 1) * 2];
                    const uint32_t* bpl = &bl[nt >> 1][(nt & 1) * 2];
                    mma16816(acc[mt][nt], ah[mt], bph);   // hi * Whi
                    mma16816(acc[mt][nt], ah[mt], bpl);   // hi * Wlo
                    mma16816(acc[mt][nt], al[mt], bph);   // lo * Whi
                }
        }
        if (c < 15) computeA(c + 1, nxt);
    }

    // epilogue
    const int gid = lane >> 2, tig = lane & 3;
    #pragma unroll
    for (int mt = 0; mt < 4; mt++) {
        #pragma unroll
        for (int nt = 0; nt < 4; nt++) {
            float* cvals = acc[mt][nt];
            int u0 = wm * 64 + mt * 16 + gid;
            int v0 = n0 + wn * 32 + nt * 8 + tig * 2;
            size_t r0 = ((size_t)bt * U_ + u0) * VO;
            size_t r1 = ((size_t)bt * U_ + u0 + 8) * VO;
            if (v0 < VO) {
                float bo = bout[v0];
                out[r0 + v0] = cvals[0] + bo;
                out[r1 + v0] = cvals[2] + bo;
            }
            if (v0 + 1 < VO) {
                float bo = bout[v0 + 1];
                out[r0 + v0 + 1] = cvals[1] + bo;
                out[r1 + v0 + 1] = cvals[3] + bo;
            }
        }
    }
}

// =====================================================================
extern "C" void kernel_launch(void* const* d_in, const int* in_sizes, int n_in,
                              void* d_out, int out_size)
{
    (void)in_sizes; (void)n_in; (void)out_size;
    const float* enc    = (const float*)d_in[0];
    const float* pred   = (const float*)d_in[1];
    const float* W_enc  = (const float*)d_in[2];
    const float* b_enc  = (const float*)d_in[3];
    const float* W_pred = (const float*)d_in[4];
    const float* b_pred = (const float*)d_in[5];
    const float* W_out  = (const float*)d_in[6];
    const float* b_out  = (const float*)d_in[7];
    float* out = (float*)d_out;

    void *pe, *pp;
    cudaGetSymbolAddress(&pe, g_enc_proj);
    cudaGetSymbolAddress(&pp, g_pred_proj);
    float* genc  = (float*)pe;
    float* gpred = (float*)pp;

    cudaFuncSetAttribute(joint_main, cudaFuncAttributeMaxDynamicSharedMemorySize, SM_TOTAL);

    dim3 pg1(JD / 64, (B_ * T_) / 64);   // 16 x 16
    proj_gemm<<<pg1, 256>>>(enc, W_enc, b_enc, genc, B_ * T_, DE, JD);
    dim3 pg2(JD / 64, (B_ * U_) / 64);   // 16 x 8
    proj_gemm<<<pg2, 256>>>(pred, W_pred, b_pred, gpred, B_ * U_, DP, JD);
    prep_w<<<(JD * NPAD + 255) / 256, 256>>>(W_out);

    dim3 grid(9, B_ * T_);               // 9 n-tiles x 1024 (b,t) tiles
    joint_main<<<grid, 256, SM_TOTAL>>>(b_out, out);
}

// round 3
// speedup vs baseline: 1.3481x; 1.3481x over previous
#include <cuda_runtime.h>
#include <cuda_bf16.h>
#include <cuda_fp16.h>
#include <stdint.h>

#define B_   4
#define T_   256
#define U_   128
#define DE   512
#define DP   640
#define JD   1024
#define VO   1025
#define NPAD 1152   // 9 n-tiles of 128

#define KC     64
#define APITCH 72    // 64 + 8 pad (fp16 elems), pitch 144B
#define BPITCH 136   // 128 + 8 pad, pitch 272B

// ---- dynamic smem layout (bytes) ----
#define SM_ENC 0                         // float[1024]          : 4096
#define SM_AHI 4096                      // 2 x half[128][72]    : 2*18432
#define SM_ALO (SM_AHI + 2*18432)        // 2 x half[128][72]
#define SM_B   (SM_ALO + 2*18432)        // 2 x half[64][136]    : 2*17408
#define SM_TOTAL (SM_B + 2*17408)        // 112640 bytes -> 2 CTAs/SM

// ---- device scratch ----
__device__ __align__(16) float g_enc_proj[B_*T_*JD];      // 4 MB
__device__ __align__(16) float g_pred_proj[B_*U_*JD];     // 2 MB
__device__ __align__(16) __half g_W16[JD*NPAD];           // [k][n] 2.36 MB

// =====================================================================
// helpers
// =====================================================================
__device__ __forceinline__ uint32_t smem_u32(const void* p) {
    return (uint32_t)__cvta_generic_to_shared(p);
}
__device__ __forceinline__ void ldm_x4(uint32_t* r, uint32_t addr) {
    asm volatile("ldmatrix.sync.aligned.m8n8.x4.shared.b16 {%0,%1,%2,%3}, [%4];"
                 : "=r"(r[0]), "=r"(r[1]), "=r"(r[2]), "=r"(r[3]) : "r"(addr));
}
__device__ __forceinline__ void ldm_x4_t(uint32_t* r, uint32_t addr) {
    asm volatile("ldmatrix.sync.aligned.m8n8.x4.trans.shared.b16 {%0,%1,%2,%3}, [%4];"
                 : "=r"(r[0]), "=r"(r[1]), "=r"(r[2]), "=r"(r[3]) : "r"(addr));
}
__device__ __forceinline__ void mma16816(float* c, const uint32_t* a, const uint32_t* b) {
    asm volatile(
        "mma.sync.aligned.m16n8k16.row.col.f32.f16.f16.f32 "
        "{%0,%1,%2,%3},{%4,%5,%6,%7},{%8,%9},{%0,%1,%2,%3};"
        : "+f"(c[0]), "+f"(c[1]), "+f"(c[2]), "+f"(c[3])
        : "r"(a[0]), "r"(a[1]), "r"(a[2]), "r"(a[3]), "r"(b[0]), "r"(b[1]));
}
__device__ __forceinline__ void cp16(void* dst_smem, const void* src) {
    uint32_t d = smem_u32(dst_smem);
    asm volatile("cp.async.cg.shared.global [%0], [%1], 16;\n" :: "r"(d), "l"(src) : "memory");
}
__device__ __forceinline__ void cp_commit() {
    asm volatile("cp.async.commit_group;\n" ::: "memory");
}
__device__ __forceinline__ void cp_wait_all() {
    asm volatile("cp.async.wait_group 0;\n" ::: "memory");
}

// =====================================================================
// kernel 1: fp32 projection GEMM  C[M,J] = A[M,K] @ W[K,J] + bias
// =====================================================================
__global__ void __launch_bounds__(256) proj_gemm(
    const float* __restrict__ A, const float* __restrict__ W,
    const float* __restrict__ bias, float* __restrict__ C,
    int M, int K, int J)
{
    __shared__ float As[16][68];
    __shared__ float Bs[16][64];
    const int tx = threadIdx.x & 15;
    const int ty = threadIdx.x >> 4;
    const int m0 = blockIdx.y * 64;
    const int n0 = blockIdx.x * 64;

    float acc[4][4] = {};

    for (int k0 = 0; k0 < K; k0 += 16) {
        {
            int t = threadIdx.x;
            int m  = t >> 2, k4 = (t & 3) * 4;
            float4 a = *(const float4*)(A + (size_t)(m0 + m) * K + k0 + k4);
            As[k4 + 0][m] = a.x; As[k4 + 1][m] = a.y;
            As[k4 + 2][m] = a.z; As[k4 + 3][m] = a.w;
            int kk = t >> 4, n4 = (t & 15) * 4;
            *(float4*)&Bs[kk][n4] = *(const float4*)(W + (size_t)(k0 + kk) * J + n0 + n4);
        }
        __syncthreads();
        #pragma unroll
        for (int k = 0; k < 16; k++) {
            float a[4], b[4];
            *(float4*)a = *(float4*)&As[k][ty * 4];
            *(float4*)b = *(float4*)&Bs[k][tx * 4];
            #pragma unroll
            for (int i = 0; i < 4; i++)
                #pragma unroll
                for (int j = 0; j < 4; j++)
                    acc[i][j] += a[i] * b[j];
        }
        __syncthreads();
    }
    #pragma unroll
    for (int i = 0; i < 4; i++) {
        int m = m0 + ty * 4 + i;
        #pragma unroll
        for (int j = 0; j < 4; j++) {
            int n = n0 + tx * 4 + j;
            C[(size_t)m * J + n] = acc[i][j] + bias[n];
        }
    }
}

// =====================================================================
// kernel 2: W_out -> fp16, padded [JD][NPAD] (k-major rows)
// =====================================================================
__global__ void prep_w(const float* __restrict__ W) {
    int idx = blockIdx.x * 256 + threadIdx.x;
    if (idx >= JD * NPAD) return;
    int j = idx / NPAD, n = idx % NPAD;
    float w = (n < VO) ? W[(size_t)j * VO + n] : 0.f;
    g_W16[idx] = __float2half_rn(w);
}

// =====================================================================
// kernel 3: fused joint: out[bt,u,v] = relu(enc[bt]+pred[b,u]) @ W_out + b_out
// fp16 2-pass split on A: acc += Ahi*W + Alo*W
// =====================================================================
__global__ void __launch_bounds__(256, 2) joint_main(
    const float* __restrict__ bout, float* __restrict__ out)
{
    extern __shared__ char sm[];
    float* enc_s = (float*)(sm + SM_ENC);

    const int bt    = blockIdx.y;          // 0..1023
    const int b     = bt >> 8;             // T = 256
    const int ntile = blockIdx.x;          // 0..8
    const int n0    = ntile * 128;
    const int t     = threadIdx.x;
    const int warp  = t >> 5;
    const int lane  = t & 31;
    const int wm    = warp >> 2;           // 0..1 (M)
    const int wn    = warp & 3;            // 0..3 (N)
    const int lr    = lane & 15;
    const int lc    = (lane >> 4) * 8;

    const float* encg  = g_enc_proj  + (size_t)bt * JD;
    const float* predg = g_pred_proj + (size_t)b * U_ * JD;

    // enc row -> smem
    *(float4*)&enc_s[t * 4] = *(const float4*)&encg[t * 4];

    auto issueB = [&](int c, int buf) {
        const __half* src = g_W16 + (size_t)(c * KC) * NPAD + n0;
        __half* dst = (__half*)(sm + SM_B + buf * 17408);
        #pragma unroll
        for (int i = 0; i < 4; i++) {
            int flat = t + 256 * i;                 // 0..1023
            int row = flat >> 4, c16 = flat & 15;   // 64 rows x 16 x 16B
            cp16(dst + row * BPITCH + c16 * 8, src + (size_t)row * NPAD + c16 * 8);
        }
        cp_commit();
    };

    auto computeA = [&](int c, int buf) {
        __half* Ahi = (__half*)(sm + SM_AHI + buf * 18432);
        __half* Alo = (__half*)(sm + SM_ALO + buf * 18432);
        const int u  = t >> 1;
        const int jh = (t & 1) * 32;
        const int j0 = c * KC + jh;
        const float4* src = (const float4*)(predg + (size_t)u * JD + j0);
        #pragma unroll
        for (int i = 0; i < 8; i++) {
            float4 p = src[i];
            float pv[4] = {p.x, p.y, p.z, p.w};
            __half2 hp[2], lp[2];
            #pragma unroll
            for (int q = 0; q < 2; q++) {
                float h0 = fmaxf(pv[2*q]     + enc_s[j0 + i * 4 + 2*q],     0.f);
                float h1 = fmaxf(pv[2*q + 1] + enc_s[j0 + i * 4 + 2*q + 1], 0.f);
                __half2 hh = __floats2half2_rn(h0, h1);
                hp[q] = hh;
                float l0 = h0 - __half2float(__low2half(hh));
                float l1 = h1 - __half2float(__high2half(hh));
                lp[q] = __floats2half2_rn(l0, l1);
            }
            int base = u * APITCH + jh + i * 4;
            *(__half2*)&Ahi[base + 0] = hp[0];
            *(__half2*)&Ahi[base + 2] = hp[1];
            *(__half2*)&Alo[base + 0] = lp[0];
            *(__half2*)&Alo[base + 2] = lp[1];
        }
    };

    float acc[4][4][4] = {};

    issueB(0, 0);
    __syncthreads();        // enc_s visible
    computeA(0, 0);

    for (int c = 0; c < 16; c++) {
        const int cur = c & 1, nxt = cur ^ 1;
        cp_wait_all();
        __syncthreads();    // A stores + B arrival visible; prev-buffer reads retired
        if (c < 15) issueB(c + 1, nxt);

        uint32_t aHiB = smem_u32(sm + SM_AHI + cur * 18432) + (uint32_t)(((wm * 64 + lr) * APITCH + lc) * 2);
        uint32_t aLoB = smem_u32(sm + SM_ALO + cur * 18432) + (uint32_t)(((wm * 64 + lr) * APITCH + lc) * 2);
        uint32_t bB   = smem_u32(sm + SM_B   + cur * 17408) + (uint32_t)((lr * BPITCH + wn * 32 + lc) * 2);

        #pragma unroll
        for (int ks = 0; ks < 4; ks++) {
            uint32_t bq[2][4];
            #pragma unroll
            for (int n2 = 0; n2 < 2; n2++)
                ldm_x4_t(bq[n2], bB + (uint32_t)((ks * 16 * BPITCH + n2 * 16) * 2));
            #pragma unroll
            for (int mt = 0; mt < 4; mt++) {
                uint32_t ah[4], al[4];
                ldm_x4(ah, aHiB + (uint32_t)((mt * 16 * APITCH + ks * 16) * 2));
                ldm_x4(al, aLoB + (uint32_t)((mt * 16 * APITCH + ks * 16) * 2));
                #pragma unroll
                for (int nt = 0; nt < 4; nt++) {
                    const uint32_t* bp = &bq[nt >> 1][(nt & 1) * 2];
                    mma16816(acc[mt][nt], ah, bp);   // hi * W
                    mma16816(acc[mt][nt], al, bp);   // lo * W
                }
            }
        }
        if (c < 15) computeA(c + 1, nxt);
    }

    // epilogue
    const int gid = lane >> 2, tig = lane & 3;
    #pragma unroll
    for (int mt = 0; mt < 4; mt++) {
        #pragma unroll
        for (int nt = 0; nt < 4; nt++) {
            float* cvals = acc[mt][nt];
            int u0 = wm * 64 + mt * 16 + gid;
            int v0 = n0 + wn * 32 + nt * 8 + tig * 2;
            size_t r0 = ((size_t)bt * U_ + u0) * VO;
            size_t r1 = ((size_t)bt * U_ + u0 + 8) * VO;
            if (v0 < VO) {
                float bo = bout[v0];
                out[r0 + v0] = cvals[0] + bo;
                out[r1 + v0] = cvals[2] + bo;
            }
            if (v0 + 1 < VO) {
                float bo = bout[v0 + 1];
                out[r0 + v0 + 1] = cvals[1] + bo;
                out[r1 + v0 + 1] = cvals[3] + bo;
            }
        }
    }
}

// =====================================================================
extern "C" void kernel_launch(void* const* d_in, const int* in_sizes, int n_in,
                              void* d_out, int out_size)
{
    (void)in_sizes; (void)n_in; (void)out_size;
    const float* enc    = (const float*)d_in[0];
    const float* pred   = (const float*)d_in[1];
    const float* W_enc  = (const float*)d_in[2];
    const float* b_enc  = (const float*)d_in[3];
    const float* W_pred = (const float*)d_in[4];
    const float* b_pred = (const float*)d_in[5];
    const float* W_out  = (const float*)d_in[6];
    const float* b_out  = (const float*)d_in[7];
    float* out = (float*)d_out;

    void *pe, *pp;
    cudaGetSymbolAddress(&pe, g_enc_proj);
    cudaGetSymbolAddress(&pp, g_pred_proj);
    float* genc  = (float*)pe;
    float* gpred = (float*)pp;

    cudaFuncSetAttribute(joint_main, cudaFuncAttributeMaxDynamicSharedMemorySize, SM_TOTAL);

    dim3 pg1(JD / 64, (B_ * T_) / 64);   // 16 x 16
    proj_gemm<<<pg1, 256>>>(enc, W_enc, b_enc, genc, B_ * T_, DE, JD);
    dim3 pg2(JD / 64, (B_ * U_) / 64);   // 16 x 8
    proj_gemm<<<pg2, 256>>>(pred, W_pred, b_pred, gpred, B_ * U_, DP, JD);
    prep_w<<<(JD * NPAD + 255) / 256, 256>>>(W_out);

    dim3 grid(9, B_ * T_);               // 9 n-tiles x 1024 (b,t) tiles
    joint_main<<<grid, 256, SM_TOTAL>>>(b_out, out);
}

// round 4
// speedup vs baseline: 1.6295x; 1.2088x over previous
#include <cuda_runtime.h>
#include <cuda_bf16.h>
#include <cuda_fp16.h>
#include <stdint.h>

#define B_   4
#define T_   256
#define U_   128
#define DE   512
#define DP   640
#define JD   1024
#define VO   1025
#define NPAD 1152   // 9 n-tiles of 128

#define KC     64
#define APITCH 72    // 64 + 8 pad (fp16 elems), pitch 144B
#define BPITCH 136   // 128 + 8 pad, pitch 272B

// ---- dynamic smem layout (bytes) ----
#define SM_ENC 0                         // float[1024]          : 4096
#define SM_A   4096                      // 2 x half[128][72]    : 2*18432
#define SM_B   (SM_A + 2*18432)          // 2 x half[64][136]    : 2*17408
#define SM_TOTAL (SM_B + 2*17408)        // 75776 bytes -> 2 CTAs/SM

// ---- device scratch ----
__device__ __align__(16) float g_enc_proj[B_*T_*JD];      // 4 MB
__device__ __align__(16) float g_pred_proj[B_*U_*JD];     // 2 MB
__device__ __align__(16) __half g_W16[JD*NPAD];           // [k][n] 2.36 MB

// =====================================================================
// helpers
// =====================================================================
__device__ __forceinline__ uint32_t smem_u32(const void* p) {
    return (uint32_t)__cvta_generic_to_shared(p);
}
__device__ __forceinline__ void ldm_x4(uint32_t* r, uint32_t addr) {
    asm volatile("ldmatrix.sync.aligned.m8n8.x4.shared.b16 {%0,%1,%2,%3}, [%4];"
                 : "=r"(r[0]), "=r"(r[1]), "=r"(r[2]), "=r"(r[3]) : "r"(addr));
}
__device__ __forceinline__ void ldm_x4_t(uint32_t* r, uint32_t addr) {
    asm volatile("ldmatrix.sync.aligned.m8n8.x4.trans.shared.b16 {%0,%1,%2,%3}, [%4];"
                 : "=r"(r[0]), "=r"(r[1]), "=r"(r[2]), "=r"(r[3]) : "r"(addr));
}
__device__ __forceinline__ void mma16816(float* c, const uint32_t* a, const uint32_t* b) {
    asm volatile(
        "mma.sync.aligned.m16n8k16.row.col.f32.f16.f16.f32 "
        "{%0,%1,%2,%3},{%4,%5,%6,%7},{%8,%9},{%0,%1,%2,%3};"
        : "+f"(c[0]), "+f"(c[1]), "+f"(c[2]), "+f"(c[3])
        : "r"(a[0]), "r"(a[1]), "r"(a[2]), "r"(a[3]), "r"(b[0]), "r"(b[1]));
}
__device__ __forceinline__ void cp16(void* dst_smem, const void* src) {
    uint32_t d = smem_u32(dst_smem);
    asm volatile("cp.async.cg.shared.global [%0], [%1], 16;\n" :: "r"(d), "l"(src) : "memory");
}
__device__ __forceinline__ void cp_commit() {
    asm volatile("cp.async.commit_group;\n" ::: "memory");
}
__device__ __forceinline__ void cp_wait_all() {
    asm volatile("cp.async.wait_group 0;\n" ::: "memory");
}

// =====================================================================
// kernel 1: fp32 projection GEMM  C[M,J] = A[M,K] @ W[K,J] + bias
// =====================================================================
__global__ void __launch_bounds__(256) proj_gemm(
    const float* __restrict__ A, const float* __restrict__ W,
    const float* __restrict__ bias, float* __restrict__ C,
    int M, int K, int J)
{
    __shared__ float As[16][68];
    __shared__ float Bs[16][64];
    const int tx = threadIdx.x & 15;
    const int ty = threadIdx.x >> 4;
    const int m0 = blockIdx.y * 64;
    const int n0 = blockIdx.x * 64;

    float acc[4][4] = {};

    for (int k0 = 0; k0 < K; k0 += 16) {
        {
            int t = threadIdx.x;
            int m  = t >> 2, k4 = (t & 3) * 4;
            float4 a = *(const float4*)(A + (size_t)(m0 + m) * K + k0 + k4);
            As[k4 + 0][m] = a.x; As[k4 + 1][m] = a.y;
            As[k4 + 2][m] = a.z; As[k4 + 3][m] = a.w;
            int kk = t >> 4, n4 = (t & 15) * 4;
            *(float4*)&Bs[kk][n4] = *(const float4*)(W + (size_t)(k0 + kk) * J + n0 + n4);
        }
        __syncthreads();
        #pragma unroll
        for (int k = 0; k < 16; k++) {
            float a[4], b[4];
            *(float4*)a = *(float4*)&As[k][ty * 4];
            *(float4*)b = *(float4*)&Bs[k][tx * 4];
            #pragma unroll
            for (int i = 0; i < 4; i++)
                #pragma unroll
                for (int j = 0; j < 4; j++)
                    acc[i][j] += a[i] * b[j];
        }
        __syncthreads();
    }
    #pragma unroll
    for (int i = 0; i < 4; i++) {
        int m = m0 + ty * 4 + i;
        #pragma unroll
        for (int j = 0; j < 4; j++) {
            int n = n0 + tx * 4 + j;
            C[(size_t)m * J + n] = acc[i][j] + bias[n];
        }
    }
}

// =====================================================================
// kernel 2: W_out -> fp16, padded [JD][NPAD] (k-major rows)
// =====================================================================
__global__ void prep_w(const float* __restrict__ W) {
    int idx = blockIdx.x * 256 + threadIdx.x;
    if (idx >= JD * NPAD) return;
    int j = idx / NPAD, n = idx % NPAD;
    float w = (n < VO) ? W[(size_t)j * VO + n] : 0.f;
    g_W16[idx] = __float2half_rn(w);
}

// =====================================================================
// kernel 3: fused joint: out[bt,u,v] = relu(enc[bt]+pred[b,u]) @ W_out + b_out
// single-pass fp16 (A and W both fp16, f32 accumulate)
// =====================================================================
__global__ void __launch_bounds__(256, 2) joint_main(
    const float* __restrict__ bout, float* __restrict__ out)
{
    extern __shared__ char sm[];
    float* enc_s = (float*)(sm + SM_ENC);

    const int bt    = blockIdx.y;          // 0..1023
    const int b     = bt >> 8;             // T = 256
    const int ntile = blockIdx.x;          // 0..8
    const int n0    = ntile * 128;
    const int t     = threadIdx.x;
    const int warp  = t >> 5;
    const int lane  = t & 31;
    const int wm    = warp >> 2;           // 0..1 (M)
    const int wn    = warp & 3;            // 0..3 (N)
    const int lr    = lane & 15;
    const int lc    = (lane >> 4) * 8;

    const float* encg  = g_enc_proj  + (size_t)bt * JD;
    const float* predg = g_pred_proj + (size_t)b * U_ * JD;

    // enc row -> smem
    *(float4*)&enc_s[t * 4] = *(const float4*)&encg[t * 4];

    auto issueB = [&](int c, int buf) {
        const __half* src = g_W16 + (size_t)(c * KC) * NPAD + n0;
        __half* dst = (__half*)(sm + SM_B + buf * 17408);
        #pragma unroll
        for (int i = 0; i < 4; i++) {
            int flat = t + 256 * i;                 // 0..1023
            int row = flat >> 4, c16 = flat & 15;   // 64 rows x 16 x 16B
            cp16(dst + row * BPITCH + c16 * 8, src + (size_t)row * NPAD + c16 * 8);
        }
        cp_commit();
    };

    auto computeA = [&](int c, int buf) {
        __half* As = (__half*)(sm + SM_A + buf * 18432);
        const int u  = t >> 1;
        const int jh = (t & 1) * 32;
        const int j0 = c * KC + jh;
        const float4* src = (const float4*)(predg + (size_t)u * JD + j0);
        #pragma unroll
        for (int i = 0; i < 8; i++) {
            float4 p = src[i];
            float h0 = fmaxf(p.x + enc_s[j0 + i * 4 + 0], 0.f);
            float h1 = fmaxf(p.y + enc_s[j0 + i * 4 + 1], 0.f);
            float h2 = fmaxf(p.z + enc_s[j0 + i * 4 + 2], 0.f);
            float h3 = fmaxf(p.w + enc_s[j0 + i * 4 + 3], 0.f);
            int base = u * APITCH + jh + i * 4;
            *(__half2*)&As[base + 0] = __floats2half2_rn(h0, h1);
            *(__half2*)&As[base + 2] = __floats2half2_rn(h2, h3);
        }
    };

    float acc[4][4][4] = {};

    issueB(0, 0);
    __syncthreads();        // enc_s visible
    computeA(0, 0);

    for (int c = 0; c < 16; c++) {
        const int cur = c & 1, nxt = cur ^ 1;
        cp_wait_all();
        __syncthreads();    // A stores + B arrival visible; prev-buffer reads retired
        if (c < 15) issueB(c + 1, nxt);

        uint32_t aB = smem_u32(sm + SM_A + cur * 18432) + (uint32_t)(((wm * 64 + lr) * APITCH + lc) * 2);
        uint32_t bB = smem_u32(sm + SM_B + cur * 17408) + (uint32_t)((lr * BPITCH + wn * 32 + lc) * 2);

        #pragma unroll
        for (int ks = 0; ks < 4; ks++) {
            uint32_t bq[2][4];
            #pragma unroll
            for (int n2 = 0; n2 < 2; n2++)
                ldm_x4_t(bq[n2], bB + (uint32_t)((ks * 16 * BPITCH + n2 * 16) * 2));
            #pragma unroll
            for (int mt = 0; mt < 4; mt++) {
                uint32_t a[4];
                ldm_x4(a, aB + (uint32_t)((mt * 16 * APITCH + ks * 16) * 2));
                #pragma unroll
                for (int nt = 0; nt < 4; nt++) {
                    const uint32_t* bp = &bq[nt >> 1][(nt & 1) * 2];
                    mma16816(acc[mt][nt], a, bp);
                }
            }
        }
        if (c < 15) computeA(c + 1, nxt);
    }

    // epilogue
    const int gid = lane >> 2, tig = lane & 3;
    #pragma unroll
    for (int mt = 0; mt < 4; mt++) {
        #pragma unroll
        for (int nt = 0; nt < 4; nt++) {
            float* cvals = acc[mt][nt];
            int u0 = wm * 64 + mt * 16 + gid;
            int v0 = n0 + wn * 32 + nt * 8 + tig * 2;
            size_t r0 = ((size_t)bt * U_ + u0) * VO;
            size_t r1 = ((size_t)bt * U_ + u0 + 8) * VO;
            if (v0 < VO) {
                float bo = bout[v0];
                out[r0 + v0] = cvals[0] + bo;
                out[r1 + v0] = cvals[2] + bo;
            }
            if (v0 + 1 < VO) {
                float bo = bout[v0 + 1];
                out[r0 + v0 + 1] = cvals[1] + bo;
                out[r1 + v0 + 1] = cvals[3] + bo;
            }
        }
    }
}

// =====================================================================
extern "C" void kernel_launch(void* const* d_in, const int* in_sizes, int n_in,
                              void* d_out, int out_size)
{
    (void)in_sizes; (void)n_in; (void)out_size;
    const float* enc    = (const float*)d_in[0];
    const float* pred   = (const float*)d_in[1];
    const float* W_enc  = (const float*)d_in[2];
    const float* b_enc  = (const float*)d_in[3];
    const float* W_pred = (const float*)d_in[4];
    const float* b_pred = (const float*)d_in[5];
    const float* W_out  = (const float*)d_in[6];
    const float* b_out  = (const float*)d_in[7];
    float* out = (float*)d_out;

    void *pe, *pp;
    cudaGetSymbolAddress(&pe, g_enc_proj);
    cudaGetSymbolAddress(&pp, g_pred_proj);
    float* genc  = (float*)pe;
    float* gpred = (float*)pp;

    cudaFuncSetAttribute(joint_main, cudaFuncAttributeMaxDynamicSharedMemorySize, SM_TOTAL);

    dim3 pg1(JD / 64, (B_ * T_) / 64);   // 16 x 16
    proj_gemm<<<pg1, 256>>>(enc, W_enc, b_enc, genc, B_ * T_, DE, JD);
    dim3 pg2(JD / 64, (B_ * U_) / 64);   // 16 x 8
    proj_gemm<<<pg2, 256>>>(pred, W_pred, b_pred, gpred, B_ * U_, DP, JD);
    prep_w<<<(JD * NPAD + 255) / 256, 256>>>(W_out);

    dim3 grid(9, B_ * T_);               // 9 n-tiles x 1024 (b,t) tiles
    joint_main<<<grid, 256, SM_TOTAL>>>(b_out, out);
}

// round 5
// speedup vs baseline: 3.1135x; 1.9107x over previous
#include <cuda_runtime.h>
#include <cuda_bf16.h>
#include <cuda_fp16.h>
#include <stdint.h>

#define B_   4
#define T_   256
#define U_   128
#define DE   512
#define DP   640
#define JD   1024
#define VO   1025

#define KC     64
#define NCHUNK 16
#define APITCH 72    // 64 + 8 pad (fp16 elems), pitch 144B
#define BPITCH 136   // 128 + 8 pad, pitch 272B

// ---- dynamic smem layout (bytes) ----
#define SM_A   0                         // 2 x half[128][72]    : 2*18432
#define SM_B   (2*18432)                 // 2 x half[64][136]    : 2*17408
#define SM_TOTAL (SM_B + 2*17408)        // 71680 bytes -> 2 CTAs/SM
// epilogue staging reuses [0, 128*132*4 = 67584) ✓

// ---- device scratch ----
__device__ __align__(16) float g_enc_proj[B_*T_*JD];      // 4 MB
__device__ __align__(16) float g_pred_proj[B_*U_*JD];     // 2 MB
__device__ __align__(16) __half g_W16[JD*1024];           // [k][n] 2 MB
__device__ __align__(16) __half g_A16[(size_t)B_*T_*NCHUNK*U_*KC];  // 256 MB

// =====================================================================
// helpers
// =====================================================================
__device__ __forceinline__ uint32_t smem_u32(const void* p) {
    return (uint32_t)__cvta_generic_to_shared(p);
}
__device__ __forceinline__ void ldm_x4(uint32_t* r, uint32_t addr) {
    asm volatile("ldmatrix.sync.aligned.m8n8.x4.shared.b16 {%0,%1,%2,%3}, [%4];"
                 : "=r"(r[0]), "=r"(r[1]), "=r"(r[2]), "=r"(r[3]) : "r"(addr));
}
__device__ __forceinline__ void ldm_x4_t(uint32_t* r, uint32_t addr) {
    asm volatile("ldmatrix.sync.aligned.m8n8.x4.trans.shared.b16 {%0,%1,%2,%3}, [%4];"
                 : "=r"(r[0]), "=r"(r[1]), "=r"(r[2]), "=r"(r[3]) : "r"(addr));
}
__device__ __forceinline__ void mma16816(float* c, const uint32_t* a, const uint32_t* b) {
    asm volatile(
        "mma.sync.aligned.m16n8k16.row.col.f32.f16.f16.f32 "
        "{%0,%1,%2,%3},{%4,%5,%6,%7},{%8,%9},{%0,%1,%2,%3};"
        : "+f"(c[0]), "+f"(c[1]), "+f"(c[2]), "+f"(c[3])
        : "r"(a[0]), "r"(a[1]), "r"(a[2]), "r"(a[3]), "r"(b[0]), "r"(b[1]));
}
__device__ __forceinline__ void cp16(void* dst_smem, const void* src) {
    uint32_t d = smem_u32(dst_smem);
    asm volatile("cp.async.cg.shared.global [%0], [%1], 16;\n" :: "r"(d), "l"(src) : "memory");
}
__device__ __forceinline__ void cp_commit() {
    asm volatile("cp.async.commit_group;\n" ::: "memory");
}
__device__ __forceinline__ void cp_wait_all() {
    asm volatile("cp.async.wait_group 0;\n" ::: "memory");
}

// =====================================================================
// kernel 1: fp32 projection GEMM  C[M,J] = A[M,K] @ W[K,J] + bias
// =====================================================================
__global__ void __launch_bounds__(256) proj_gemm(
    const float* __restrict__ A, const float* __restrict__ W,
    const float* __restrict__ bias, float* __restrict__ C,
    int M, int K, int J)
{
    __shared__ float As[16][68];
    __shared__ float Bs[16][64];
    const int tx = threadIdx.x & 15;
    const int ty = threadIdx.x >> 4;
    const int m0 = blockIdx.y * 64;
    const int n0 = blockIdx.x * 64;

    float acc[4][4] = {};

    for (int k0 = 0; k0 < K; k0 += 16) {
        {
            int t = threadIdx.x;
            int m  = t >> 2, k4 = (t & 3) * 4;
            float4 a = *(const float4*)(A + (size_t)(m0 + m) * K + k0 + k4);
            As[k4 + 0][m] = a.x; As[k4 + 1][m] = a.y;
            As[k4 + 2][m] = a.z; As[k4 + 3][m] = a.w;
            int kk = t >> 4, n4 = (t & 15) * 4;
            *(float4*)&Bs[kk][n4] = *(const float4*)(W + (size_t)(k0 + kk) * J + n0 + n4);
        }
        __syncthreads();
        #pragma unroll
        for (int k = 0; k < 16; k++) {
            float a[4], b[4];
            *(float4*)a = *(float4*)&As[k][ty * 4];
            *(float4*)b = *(float4*)&Bs[k][tx * 4];
            #pragma unroll
            for (int i = 0; i < 4; i++)
                #pragma unroll
                for (int j = 0; j < 4; j++)
                    acc[i][j] += a[i] * b[j];
        }
        __syncthreads();
    }
    #pragma unroll
    for (int i = 0; i < 4; i++) {
        int m = m0 + ty * 4 + i;
        #pragma unroll
        for (int j = 0; j < 4; j++) {
            int n = n0 + tx * 4 + j;
            C[(size_t)m * J + n] = acc[i][j] + bias[n];
        }
    }
}

// =====================================================================
// kernel 2: W_out[:, 0:1024] -> fp16 [k][n]
// =====================================================================
__global__ void prep_w(const float* __restrict__ W) {
    int idx = blockIdx.x * 256 + threadIdx.x;
    if (idx >= JD * 1024) return;
    int j = idx >> 10, n = idx & 1023;
    g_W16[idx] = __float2half_rn(W[(size_t)j * VO + n]);
}

// =====================================================================
// kernel 3: precompute fp16 joint activations
// g_A16[((bt*16 + c)*128 + u)*64 + jj] = fp16(relu(enc[bt,j] + pred[b,u,j]))
// grid 1024 (bt), 256 threads: thread = (u = t>>1, half = t&1)
// =====================================================================
__global__ void __launch_bounds__(256) precompute_A()
{
    __shared__ float enc_s[JD];
    const int bt = blockIdx.x;
    const int b  = bt >> 8;
    const int t  = threadIdx.x;
    ((float4*)enc_s)[t] = ((const float4*)(g_enc_proj + (size_t)bt * JD))[t];
    __syncthreads();

    const int u  = t >> 1;
    const int jh = (t & 1) * 32;
    const float* prow = g_pred_proj + ((size_t)(b * U_ + u)) * JD;

    #pragma unroll 4
    for (int c = 0; c < NCHUNK; c++) {
        const int j0 = c * KC + jh;
        const float4* p4 = (const float4*)(prow + j0);
        __half* dst = g_A16 + (((size_t)bt * NCHUNK + c) * U_ + u) * KC + jh;
        #pragma unroll
        for (int q = 0; q < 4; q++) {
            float4 pa = p4[2 * q], pb = p4[2 * q + 1];
            float h0 = fmaxf(pa.x + enc_s[j0 + q * 8 + 0], 0.f);
            float h1 = fmaxf(pa.y + enc_s[j0 + q * 8 + 1], 0.f);
            float h2 = fmaxf(pa.z + enc_s[j0 + q * 8 + 2], 0.f);
            float h3 = fmaxf(pa.w + enc_s[j0 + q * 8 + 3], 0.f);
            float h4 = fmaxf(pb.x + enc_s[j0 + q * 8 + 4], 0.f);
            float h5 = fmaxf(pb.y + enc_s[j0 + q * 8 + 5], 0.f);
            float h6 = fmaxf(pb.z + enc_s[j0 + q * 8 + 6], 0.f);
            float h7 = fmaxf(pb.w + enc_s[j0 + q * 8 + 7], 0.f);
            __half2 v0 = __floats2half2_rn(h0, h1);
            __half2 v1 = __floats2half2_rn(h2, h3);
            __half2 v2 = __floats2half2_rn(h4, h5);
            __half2 v3 = __floats2half2_rn(h6, h7);
            *(uint4*)(dst + q * 8) = make_uint4(
                *(uint32_t*)&v0, *(uint32_t*)&v1, *(uint32_t*)&v2, *(uint32_t*)&v3);
        }
    }
}

// =====================================================================
// kernel 4: fused joint GEMM (cols 0..1023): cp.async A16 + W16, mma f16
// =====================================================================
__global__ void __launch_bounds__(256, 2) joint_main(
    const float* __restrict__ bout, float* __restrict__ out)
{
    extern __shared__ char sm[];

    const int bt    = blockIdx.y;          // 0..1023
    const int ntile = blockIdx.x;          // 0..7
    const int n0    = ntile * 128;
    const int t     = threadIdx.x;
    const int warp  = t >> 5;
    const int lane  = t & 31;
    const int wm    = warp >> 2;           // 0..1 (M)
    const int wn    = warp & 3;            // 0..3 (N)
    const int lr    = lane & 15;
    const int lc    = (lane >> 4) * 8;

    const __half* Abase = g_A16 + (size_t)bt * NCHUNK * U_ * KC;

    auto issueAB = [&](int c, int buf) {
        // A: 128 rows x 64 fp16 (contiguous 16KB), 4 granules/thread
        const __half* asrc = Abase + (size_t)c * U_ * KC;
        __half* adst = (__half*)(sm + SM_A + buf * 18432);
        #pragma unroll
        for (int i = 0; i < 4; i++) {
            int flat = t + 256 * i;                 // 0..1023
            int row = flat >> 3, g = flat & 7;      // 128 rows x 8 x 16B
            cp16(adst + row * APITCH + g * 8, asrc + row * KC + g * 8);
        }
        // B: 64 k-rows x 128 n fp16
        const __half* bsrc = g_W16 + (size_t)(c * KC) * 1024 + n0;
        __half* bdst = (__half*)(sm + SM_B + buf * 17408);
        #pragma unroll
        for (int i = 0; i < 4; i++) {
            int flat = t + 256 * i;                 // 0..1023
            int row = flat >> 4, c16 = flat & 15;   // 64 rows x 16 x 16B
            cp16(bdst + row * BPITCH + c16 * 8, bsrc + (size_t)row * 1024 + c16 * 8);
        }
        cp_commit();
    };

    float acc[4][4][4] = {};

    issueAB(0, 0);

    for (int c = 0; c < NCHUNK; c++) {
        const int cur = c & 1, nxt = cur ^ 1;
        cp_wait_all();
        __syncthreads();
        if (c < NCHUNK - 1) issueAB(c + 1, nxt);

        uint32_t aB = smem_u32(sm + SM_A + cur * 18432) + (uint32_t)(((wm * 64 + lr) * APITCH + lc) * 2);
        uint32_t bB = smem_u32(sm + SM_B + cur * 17408) + (uint32_t)((lr * BPITCH + wn * 32 + lc) * 2);

        #pragma unroll
        for (int ks = 0; ks < 4; ks++) {
            uint32_t bq[2][4];
            #pragma unroll
            for (int n2 = 0; n2 < 2; n2++)
                ldm_x4_t(bq[n2], bB + (uint32_t)((ks * 16 * BPITCH + n2 * 16) * 2));
            #pragma unroll
            for (int mt = 0; mt < 4; mt++) {
                uint32_t a[4];
                ldm_x4(a, aB + (uint32_t)((mt * 16 * APITCH + ks * 16) * 2));
                #pragma unroll
                for (int nt = 0; nt < 4; nt++) {
                    const uint32_t* bp = &bq[nt >> 1][(nt & 1) * 2];
                    mma16816(acc[mt][nt], a, bp);
                }
            }
        }
        __syncthreads();   // all warps done reading cur before next overwrite cycle
    }

    // ---- coalesced epilogue: stage f32 tile in smem, then contiguous STG ----
    float* stg = (float*)sm;               // 128 x 132 floats = 67584 B
    const int gid = lane >> 2, tig = lane & 3;
    #pragma unroll
    for (int mt = 0; mt < 4; mt++) {
        #pragma unroll
        for (int nt = 0; nt < 4; nt++) {
            float* cv = acc[mt][nt];
            int u0 = wm * 64 + mt * 16 + gid;
            int c0 = wn * 32 + nt * 8 + tig * 2;
            *(float2*)&stg[u0 * 132 + c0]       = make_float2(cv[0], cv[1]);
            *(float2*)&stg[(u0 + 8) * 132 + c0] = make_float2(cv[2], cv[3]);
        }
    }
    __syncthreads();

    float bo[4];
    #pragma unroll
    for (int i = 0; i < 4; i++) bo[i] = bout[n0 + i * 32 + lane];

    #pragma unroll
    for (int ri = 0; ri < 16; ri++) {
        int row = warp * 16 + ri;
        float* orow = out + ((size_t)bt * U_ + row) * VO + n0;
        #pragma unroll
        for (int i = 0; i < 4; i++)
            orow[i * 32 + lane] = stg[row * 132 + i * 32 + lane] + bo[i];
    }
}

// =====================================================================
// kernel 5: blank column v=1024: out[bt,u,1024] = A16[bt,u,:] . W_out[:,1024] + b
// =====================================================================
__global__ void __launch_bounds__(256) blank_col(
    const float* __restrict__ Wout, const float* __restrict__ bout,
    float* __restrict__ out)
{
    __shared__ float w_s[JD];
    const int bt = blockIdx.x;
    const int t  = threadIdx.x;
    for (int i = t; i < JD; i += 256) w_s[i] = Wout[(size_t)i * VO + (VO - 1)];
    __syncthreads();

    const int u = t >> 1, h = t & 1;
    float acc = 0.f;
    #pragma unroll 2
    for (int c = 0; c < NCHUNK; c++) {
        const __half* a = g_A16 + (((size_t)bt * NCHUNK + c) * U_ + u) * KC + h * 32;
        const float* w = w_s + c * KC + h * 32;
        const uint4* p = (const uint4*)a;
        #pragma unroll
        for (int q = 0; q < 4; q++) {
            uint4 v = p[q];
            __half2 h0 = *(__half2*)&v.x, h1 = *(__half2*)&v.y;
            __half2 h2 = *(__half2*)&v.z, h3 = *(__half2*)&v.w;
            float2 f0 = __half22float2(h0), f1 = __half22float2(h1);
            float2 f2 = __half22float2(h2), f3 = __half22float2(h3);
            acc += f0.x * w[q*8+0] + f0.y * w[q*8+1]
                 + f1.x * w[q*8+2] + f1.y * w[q*8+3]
                 + f2.x * w[q*8+4] + f2.y * w[q*8+5]
                 + f3.x * w[q*8+6] + f3.y * w[q*8+7];
        }
    }
    acc += __shfl_xor_sync(0xffffffffu, acc, 1);
    if (h == 0)
        out[((size_t)bt * U_ + u) * VO + (VO - 1)] = acc + bout[VO - 1];
}

// =====================================================================
extern "C" void kernel_launch(void* const* d_in, const int* in_sizes, int n_in,
                              void* d_out, int out_size)
{
    (void)in_sizes; (void)n_in; (void)out_size;
    const float* enc    = (const float*)d_in[0];
    const float* pred   = (const float*)d_in[1];
    const float* W_enc  = (const float*)d_in[2];
    const float* b_enc  = (const float*)d_in[3];
    const float* W_pred = (const float*)d_in[4];
    const float* b_pred = (const float*)d_in[5];
    const float* W_out  = (const float*)d_in[6];
    const float* b_out  = (const float*)d_in[7];
    float* out = (float*)d_out;

    void *pe, *pp;
    cudaGetSymbolAddress(&pe, g_enc_proj);
    cudaGetSymbolAddress(&pp, g_pred_proj);
    float* genc  = (float*)pe;
    float* gpred = (float*)pp;

    cudaFuncSetAttribute(joint_main, cudaFuncAttributeMaxDynamicSharedMemorySize, SM_TOTAL);

    dim3 pg1(JD / 64, (B_ * T_) / 64);
    proj_gemm<<<pg1, 256>>>(enc, W_enc, b_enc, genc, B_ * T_, DE, JD);
    dim3 pg2(JD / 64, (B_ * U_) / 64);
    proj_gemm<<<pg2, 256>>>(pred, W_pred, b_pred, gpred, B_ * U_, DP, JD);
    prep_w<<<(JD * 1024 + 255) / 256, 256>>>(W_out);
    precompute_A<<<B_ * T_, 256>>>();

    dim3 grid(8, B_ * T_);               // 8 n-tiles x 1024 (b,t) tiles
    joint_main<<<grid, 256, SM_TOTAL>>>(b_out, out);
    blank_col<<<B_ * T_, 256>>>(W_out, b_out, out);
}

// round 6
// speedup vs baseline: 3.4712x; 1.1149x over previous
#include <cuda_runtime.h>
#include <cuda_bf16.h>
#include <cuda_fp16.h>
#include <stdint.h>

#define B_   4
#define T_   256
#define U_   128
#define DE   512
#define DP   640
#define JD   1024
#define VO   1025

#define KC     64
#define NCHUNK 16
#define APITCH 72    // 64 + 8 pad (fp16 elems), pitch 144B
#define BPITCH 136   // 128 + 8 pad, pitch 272B

// ---- dynamic smem layout (bytes) ----
#define SM_A   0                         // 2 x half[128][72]    : 2*18432
#define SM_B   (2*18432)                 // 2 x half[64][136]    : 2*17408
#define SM_TOTAL (SM_B + 2*17408)        // 71680 bytes -> 2 CTAs/SM
// epilogue staging reuses [0, 128*132*4 = 67584) ✓

// ---- device scratch ----
__device__ __align__(16) float g_enc_proj[B_*T_*JD];      // 4 MB
__device__ __align__(16) float g_pred_proj[B_*U_*JD];     // 2 MB
__device__ __align__(16) __half g_W16[JD*1024];           // [k][n] 2 MB
__device__ __align__(16) __half g_A16[(size_t)B_*T_*NCHUNK*U_*KC];  // 256 MB

// =====================================================================
// helpers
// =====================================================================
__device__ __forceinline__ uint32_t smem_u32(const void* p) {
    return (uint32_t)__cvta_generic_to_shared(p);
}
__device__ __forceinline__ void ldm_x4(uint32_t* r, uint32_t addr) {
    asm volatile("ldmatrix.sync.aligned.m8n8.x4.shared.b16 {%0,%1,%2,%3}, [%4];"
                 : "=r"(r[0]), "=r"(r[1]), "=r"(r[2]), "=r"(r[3]) : "r"(addr));
}
__device__ __forceinline__ void ldm_x4_t(uint32_t* r, uint32_t addr) {
    asm volatile("ldmatrix.sync.aligned.m8n8.x4.trans.shared.b16 {%0,%1,%2,%3}, [%4];"
                 : "=r"(r[0]), "=r"(r[1]), "=r"(r[2]), "=r"(r[3]) : "r"(addr));
}
__device__ __forceinline__ void mma16816(float* c, const uint32_t* a, const uint32_t* b) {
    asm volatile(
        "mma.sync.aligned.m16n8k16.row.col.f32.f16.f16.f32 "
        "{%0,%1,%2,%3},{%4,%5,%6,%7},{%8,%9},{%0,%1,%2,%3};"
        : "+f"(c[0]), "+f"(c[1]), "+f"(c[2]), "+f"(c[3])
        : "r"(a[0]), "r"(a[1]), "r"(a[2]), "r"(a[3]), "r"(b[0]), "r"(b[1]));
}
__device__ __forceinline__ void cp16(void* dst_smem, const void* src) {
    uint32_t d = smem_u32(dst_smem);
    asm volatile("cp.async.cg.shared.global [%0], [%1], 16;\n" :: "r"(d), "l"(src) : "memory");
}
__device__ __forceinline__ void cp_commit() {
    asm volatile("cp.async.commit_group;\n" ::: "memory");
}
__device__ __forceinline__ void cp_wait_all() {
    asm volatile("cp.async.wait_group 0;\n" ::: "memory");
}

// =====================================================================
// kernel 1: fp32 projection GEMM  C[M,J] = A[M,K] @ W[K,J] + bias
// =====================================================================
__global__ void __launch_bounds__(256) proj_gemm(
    const float* __restrict__ A, const float* __restrict__ W,
    const float* __restrict__ bias, float* __restrict__ C,
    int M, int K, int J)
{
    __shared__ float As[16][68];
    __shared__ float Bs[16][64];
    const int tx = threadIdx.x & 15;
    const int ty = threadIdx.x >> 4;
    const int m0 = blockIdx.y * 64;
    const int n0 = blockIdx.x * 64;

    float acc[4][4] = {};

    for (int k0 = 0; k0 < K; k0 += 16) {
        {
            int t = threadIdx.x;
            int m  = t >> 2, k4 = (t & 3) * 4;
            float4 a = *(const float4*)(A + (size_t)(m0 + m) * K + k0 + k4);
            As[k4 + 0][m] = a.x; As[k4 + 1][m] = a.y;
            As[k4 + 2][m] = a.z; As[k4 + 3][m] = a.w;
            int kk = t >> 4, n4 = (t & 15) * 4;
            *(float4*)&Bs[kk][n4] = *(const float4*)(W + (size_t)(k0 + kk) * J + n0 + n4);
        }
        __syncthreads();
        #pragma unroll
        for (int k = 0; k < 16; k++) {
            float a[4], b[4];
            *(float4*)a = *(float4*)&As[k][ty * 4];
            *(float4*)b = *(float4*)&Bs[k][tx * 4];
            #pragma unroll
            for (int i = 0; i < 4; i++)
                #pragma unroll
                for (int j = 0; j < 4; j++)
                    acc[i][j] += a[i] * b[j];
        }
        __syncthreads();
    }
    #pragma unroll
    for (int i = 0; i < 4; i++) {
        int m = m0 + ty * 4 + i;
        #pragma unroll
        for (int j = 0; j < 4; j++) {
            int n = n0 + tx * 4 + j;
            C[(size_t)m * J + n] = acc[i][j] + bias[n];
        }
    }
}

// =====================================================================
// kernel 2: W_out[:, 0:1024] -> fp16 [k][n]
// =====================================================================
__global__ void prep_w(const float* __restrict__ W) {
    int idx = blockIdx.x * 256 + threadIdx.x;
    if (idx >= JD * 1024) return;
    int j = idx >> 10, n = idx & 1023;
    g_W16[idx] = __float2half_rn(W[(size_t)j * VO + n]);
}

// =====================================================================
// kernel 3: precompute fp16 joint activations (coalesced) + blank column
// g_A16[((bt*16 + c)*128 + u)*64 + jj] = fp16(relu(enc[bt,j] + pred[b,u,j]))
// out[bt,u,1024] = sum_j relu(...) * W_out[j,1024] + b_out[1024]   (fp32)
// Mapping: warp covers 4 rows x 8 granules (4 contiguous 128B lines/store).
// =====================================================================
__global__ void __launch_bounds__(256) precompute_A(
    const float* __restrict__ Wout, const float* __restrict__ bout,
    float* __restrict__ out)
{
    __shared__ float enc_s[JD];
    __shared__ float wb_s[JD];
    const int bt   = blockIdx.x;
    const int b    = bt >> 8;
    const int t    = threadIdx.x;
    const int warp = t >> 5;
    const int lane = t & 31;
    const int g    = lane & 7;          // granule (8 fp16 = 16B)
    const int rsub = lane >> 3;         // 0..3 row-in-warp

    ((float4*)enc_s)[t] = ((const float4*)(g_enc_proj + (size_t)bt * JD))[t];
    for (int i = t; i < JD; i += 256)
        wb_s[i] = Wout[(size_t)i * VO + (VO - 1)];
    __syncthreads();

    const float bias_bl = bout[VO - 1];

    #pragma unroll
    for (int p = 0; p < 4; p++) {
        const int u = p * 32 + warp * 4 + rsub;
        const float* prow = g_pred_proj + ((size_t)(b * U_ + u)) * JD;
        float accb = 0.f;
        #pragma unroll 4
        for (int c = 0; c < NCHUNK; c++) {
            const int j0 = c * KC + g * 8;
            float4 pa = *(const float4*)(prow + j0);
            float4 pb = *(const float4*)(prow + j0 + 4);
            float h0 = fmaxf(pa.x + enc_s[j0 + 0], 0.f);
            float h1 = fmaxf(pa.y + enc_s[j0 + 1], 0.f);
            float h2 = fmaxf(pa.z + enc_s[j0 + 2], 0.f);
            float h3 = fmaxf(pa.w + enc_s[j0 + 3], 0.f);
            float h4 = fmaxf(pb.x + enc_s[j0 + 4], 0.f);
            float h5 = fmaxf(pb.y + enc_s[j0 + 5], 0.f);
            float h6 = fmaxf(pb.z + enc_s[j0 + 6], 0.f);
            float h7 = fmaxf(pb.w + enc_s[j0 + 7], 0.f);
            accb += h0 * wb_s[j0 + 0] + h1 * wb_s[j0 + 1]
                  + h2 * wb_s[j0 + 2] + h3 * wb_s[j0 + 3]
                  + h4 * wb_s[j0 + 4] + h5 * wb_s[j0 + 5]
                  + h6 * wb_s[j0 + 6] + h7 * wb_s[j0 + 7];
            __half2 v0 = __floats2half2_rn(h0, h1);
            __half2 v1 = __floats2half2_rn(h2, h3);
            __half2 v2 = __floats2half2_rn(h4, h5);
            __half2 v3 = __floats2half2_rn(h6, h7);
            __half* dst = g_A16 + (((size_t)bt * NCHUNK + c) * U_ + u) * KC + g * 8;
            *(uint4*)dst = make_uint4(
                *(uint32_t*)&v0, *(uint32_t*)&v1, *(uint32_t*)&v2, *(uint32_t*)&v3);
        }
        // reduce over the 8 granule-lanes sharing row u
        accb += __shfl_xor_sync(0xffffffffu, accb, 1);
        accb += __shfl_xor_sync(0xffffffffu, accb, 2);
        accb += __shfl_xor_sync(0xffffffffu, accb, 4);
        if (g == 0)
            out[((size_t)bt * U_ + u) * VO + (VO - 1)] = accb + bias_bl;
    }
}

// =====================================================================
// kernel 4: fused joint GEMM (cols 0..1023): cp.async A16 + W16, mma f16
// =====================================================================
__global__ void __launch_bounds__(256, 2) joint_main(
    const float* __restrict__ bout, float* __restrict__ out)
{
    extern __shared__ char sm[];

    const int bt    = blockIdx.y;          // 0..1023
    const int ntile = blockIdx.x;          // 0..7
    const int n0    = ntile * 128;
    const int t     = threadIdx.x;
    const int warp  = t >> 5;
    const int lane  = t & 31;
    const int wm    = warp >> 2;           // 0..1 (M)
    const int wn    = warp & 3;            // 0..3 (N)
    const int lr    = lane & 15;
    const int lc    = (lane >> 4) * 8;

    const __half* Abase = g_A16 + (size_t)bt * NCHUNK * U_ * KC;

    auto issueAB = [&](int c, int buf) {
        // A: 128 rows x 64 fp16 (contiguous 16KB), 4 granules/thread
        const __half* asrc = Abase + (size_t)c * U_ * KC;
        __half* adst = (__half*)(sm + SM_A + buf * 18432);
        #pragma unroll
        for (int i = 0; i < 4; i++) {
            int flat = t + 256 * i;                 // 0..1023
            int row = flat >> 3, g = flat & 7;      // 128 rows x 8 x 16B
            cp16(adst + row * APITCH + g * 8, asrc + row * KC + g * 8);
        }
        // B: 64 k-rows x 128 n fp16
        const __half* bsrc = g_W16 + (size_t)(c * KC) * 1024 + n0;
        __half* bdst = (__half*)(sm + SM_B + buf * 17408);
        #pragma unroll
        for (int i = 0; i < 4; i++) {
            int flat = t + 256 * i;                 // 0..1023
            int row = flat >> 4, c16 = flat & 15;   // 64 rows x 16 x 16B
            cp16(bdst + row * BPITCH + c16 * 8, bsrc + (size_t)row * 1024 + c16 * 8);
        }
        cp_commit();
    };

    float acc[4][4][4] = {};

    issueAB(0, 0);

    for (int c = 0; c < NCHUNK; c++) {
        const int cur = c & 1, nxt = cur ^ 1;
        cp_wait_all();
        __syncthreads();
        if (c < NCHUNK - 1) issueAB(c + 1, nxt);

        uint32_t aB = smem_u32(sm + SM_A + cur * 18432) + (uint32_t)(((wm * 64 + lr) * APITCH + lc) * 2);
        uint32_t bB = smem_u32(sm + SM_B + cur * 17408) + (uint32_t)((lr * BPITCH + wn * 32 + lc) * 2);

        #pragma unroll
        for (int ks = 0; ks < 4; ks++) {
            uint32_t bq[2][4];
            #pragma unroll
            for (int n2 = 0; n2 < 2; n2++)
                ldm_x4_t(bq[n2], bB + (uint32_t)((ks * 16 * BPITCH + n2 * 16) * 2));
            #pragma unroll
            for (int mt = 0; mt < 4; mt++) {
                uint32_t a[4];
                ldm_x4(a, aB + (uint32_t)((mt * 16 * APITCH + ks * 16) * 2));
                #pragma unroll
                for (int nt = 0; nt < 4; nt++) {
                    const uint32_t* bp = &bq[nt >> 1][(nt & 1) * 2];
                    mma16816(acc[mt][nt], a, bp);
                }
            }
        }
        __syncthreads();   // all warps done reading cur before next overwrite cycle
    }

    // ---- coalesced epilogue: stage f32 tile in smem, then contiguous STG ----
    float* stg = (float*)sm;               // 128 x 132 floats = 67584 B
    const int gid = lane >> 2, tig = lane & 3;
    #pragma unroll
    for (int mt = 0; mt < 4; mt++) {
        #pragma unroll
        for (int nt = 0; nt < 4; nt++) {
            float* cv = acc[mt][nt];
            int u0 = wm * 64 + mt * 16 + gid;
            int c0 = wn * 32 + nt * 8 + tig * 2;
            *(float2*)&stg[u0 * 132 + c0]       = make_float2(cv[0], cv[1]);
            *(float2*)&stg[(u0 + 8) * 132 + c0] = make_float2(cv[2], cv[3]);
        }
    }
    __syncthreads();

    float bo[4];
    #pragma unroll
    for (int i = 0; i < 4; i++) bo[i] = bout[n0 + i * 32 + lane];

    #pragma unroll
    for (int ri = 0; ri < 16; ri++) {
        int row = warp * 16 + ri;
        float* orow = out + ((size_t)bt * U_ + row) * VO + n0;
        #pragma unroll
        for (int i = 0; i < 4; i++)
            orow[i * 32 + lane] = stg[row * 132 + i * 32 + lane] + bo[i];
    }
}

// =====================================================================
extern "C" void kernel_launch(void* const* d_in, const int* in_sizes, int n_in,
                              void* d_out, int out_size)
{
    (void)in_sizes; (void)n_in; (void)out_size;
    const float* enc    = (const float*)d_in[0];
    const float* pred   = (const float*)d_in[1];
    const float* W_enc  = (const float*)d_in[2];
    const float* b_enc  = (const float*)d_in[3];
    const float* W_pred = (const float*)d_in[4];
    const float* b_pred = (const float*)d_in[5];
    const float* W_out  = (const float*)d_in[6];
    const float* b_out  = (const float*)d_in[7];
    float* out = (float*)d_out;

    void *pe, *pp;
    cudaGetSymbolAddress(&pe, g_enc_proj);
    cudaGetSymbolAddress(&pp, g_pred_proj);
    float* genc  = (float*)pe;
    float* gpred = (float*)pp;

    cudaFuncSetAttribute(joint_main, cudaFuncAttributeMaxDynamicSharedMemorySize, SM_TOTAL);

    dim3 pg1(JD / 64, (B_ * T_) / 64);
    proj_gemm<<<pg1, 256>>>(enc, W_enc, b_enc, genc, B_ * T_, DE, JD);
    dim3 pg2(JD / 64, (B_ * U_) / 64);
    proj_gemm<<<pg2, 256>>>(pred, W_pred, b_pred, gpred, B_ * U_, DP, JD);
    prep_w<<<(JD * 1024 + 255) / 256, 256>>>(W_out);
    precompute_A<<<B_ * T_, 256>>>(W_out, b_out, out);

    dim3 grid(8, B_ * T_);               // 8 n-tiles x 1024 (b,t) tiles
    joint_main<<<grid, 256, SM_TOTAL>>>(b_out, out);
}

// round 7
// speedup vs baseline: 3.4767x; 1.0016x over previous
#include <cuda_runtime.h>
#include <cuda_bf16.h>
#include <cuda_fp16.h>
#include <stdint.h>

#define B_   4
#define T_   256
#define U_   128
#define DE   512
#define DP   640
#define JD   1024
#define VO   1025

#define KC     64
#define NCHUNK 16
#define APITCH 72    // 64 + 8 pad (fp16 elems), pitch 144B
#define BPITCH 136   // 128 + 8 pad, pitch 272B

// ---- dynamic smem layout (bytes) ----
#define SM_A   0                         // 2 x half[128][72]    : 2*18432
#define SM_B   (2*18432)                 // 2 x half[64][136]    : 2*17408
#define SM_TOTAL (SM_B + 2*17408)        // 71680 bytes -> 2 CTAs/SM
// epilogue staging reuses [0, 128*132*4 = 67584) ✓

// ---- device scratch ----
__device__ __align__(16) float g_enc_proj[B_*T_*JD];      // 4 MB
__device__ __align__(16) float g_pred_proj[B_*U_*JD];     // 2 MB
__device__ __align__(16) __half g_W16[JD*1024];           // [k][n] 2 MB
__device__ __align__(16) __half g_A16[(size_t)B_*T_*NCHUNK*U_*KC];  // 256 MB

// =====================================================================
// helpers
// =====================================================================
__device__ __forceinline__ uint32_t smem_u32(const void* p) {
    return (uint32_t)__cvta_generic_to_shared(p);
}
__device__ __forceinline__ void ldm_x4(uint32_t* r, uint32_t addr) {
    asm volatile("ldmatrix.sync.aligned.m8n8.x4.shared.b16 {%0,%1,%2,%3}, [%4];"
                 : "=r"(r[0]), "=r"(r[1]), "=r"(r[2]), "=r"(r[3]) : "r"(addr));
}
__device__ __forceinline__ void ldm_x4_t(uint32_t* r, uint32_t addr) {
    asm volatile("ldmatrix.sync.aligned.m8n8.x4.trans.shared.b16 {%0,%1,%2,%3}, [%4];"
                 : "=r"(r[0]), "=r"(r[1]), "=r"(r[2]), "=r"(r[3]) : "r"(addr));
}
__device__ __forceinline__ void mma16816(float* c, const uint32_t* a, const uint32_t* b) {
    asm volatile(
        "mma.sync.aligned.m16n8k16.row.col.f32.f16.f16.f32 "
        "{%0,%1,%2,%3},{%4,%5,%6,%7},{%8,%9},{%0,%1,%2,%3};"
        : "+f"(c[0]), "+f"(c[1]), "+f"(c[2]), "+f"(c[3])
        : "r"(a[0]), "r"(a[1]), "r"(a[2]), "r"(a[3]), "r"(b[0]), "r"(b[1]));
}
__device__ __forceinline__ void cp16(void* dst_smem, const void* src) {
    uint32_t d = smem_u32(dst_smem);
    asm volatile("cp.async.cg.shared.global [%0], [%1], 16;\n" :: "r"(d), "l"(src) : "memory");
}
__device__ __forceinline__ void cp_commit() {
    asm volatile("cp.async.commit_group;\n" ::: "memory");
}
__device__ __forceinline__ void cp_wait_all() {
    asm volatile("cp.async.wait_group 0;\n" ::: "memory");
}

// =====================================================================
// kernel 1: fp32 projection GEMM  C[M,J] = A[M,K] @ W[K,J] + bias
// =====================================================================
__global__ void __launch_bounds__(256) proj_gemm(
    const float* __restrict__ A, const float* __restrict__ W,
    const float* __restrict__ bias, float* __restrict__ C,
    int M, int K, int J)
{
    __shared__ float As[16][68];
    __shared__ float Bs[16][64];
    const int tx = threadIdx.x & 15;
    const int ty = threadIdx.x >> 4;
    const int m0 = blockIdx.y * 64;
    const int n0 = blockIdx.x * 64;

    float acc[4][4] = {};

    for (int k0 = 0; k0 < K; k0 += 16) {
        {
            int t = threadIdx.x;
            int m  = t >> 2, k4 = (t & 3) * 4;
            float4 a = *(const float4*)(A + (size_t)(m0 + m) * K + k0 + k4);
            As[k4 + 0][m] = a.x; As[k4 + 1][m] = a.y;
            As[k4 + 2][m] = a.z; As[k4 + 3][m] = a.w;
            int kk = t >> 4, n4 = (t & 15) * 4;
            *(float4*)&Bs[kk][n4] = *(const float4*)(W + (size_t)(k0 + kk) * J + n0 + n4);
        }
        __syncthreads();
        #pragma unroll
        for (int k = 0; k < 16; k++) {
            float a[4], b[4];
            *(float4*)a = *(float4*)&As[k][ty * 4];
            *(float4*)b = *(float4*)&Bs[k][tx * 4];
            #pragma unroll
            for (int i = 0; i < 4; i++)
                #pragma unroll
                for (int j = 0; j < 4; j++)
                    acc[i][j] += a[i] * b[j];
        }
        __syncthreads();
    }
    #pragma unroll
    for (int i = 0; i < 4; i++) {
        int m = m0 + ty * 4 + i;
        #pragma unroll
        for (int j = 0; j < 4; j++) {
            int n = n0 + tx * 4 + j;
            C[(size_t)m * J + n] = acc[i][j] + bias[n];
        }
    }
}

// =====================================================================
// kernel 2: W_out[:, 0:1024] -> fp16 [k][n]
// =====================================================================
__global__ void prep_w(const float* __restrict__ W) {
    int idx = blockIdx.x * 256 + threadIdx.x;
    if (idx >= JD * 1024) return;
    int j = idx >> 10, n = idx & 1023;
    g_W16[idx] = __float2half_rn(W[(size_t)j * VO + n]);
}

// =====================================================================
// kernel 3: precompute fp16 joint activations (coalesced) + blank column
// g_A16[((bt*16 + c)*128 + u)*64 + jj] = fp16(relu(enc[bt,j] + pred[b,u,j]))
// out[bt,u,1024] = sum_j relu(...) * W_out[j,1024] + b_out[1024]   (fp32)
// Mapping: warp covers 4 rows x 8 granules (4 contiguous 128B lines/store).
// =====================================================================
__global__ void __launch_bounds__(256) precompute_A(
    const float* __restrict__ Wout, const float* __restrict__ bout,
    float* __restrict__ out)
{
    __shared__ float enc_s[JD];
    __shared__ float wb_s[JD];
    const int bt   = blockIdx.x;
    const int b    = bt >> 8;
    const int t    = threadIdx.x;
    const int warp = t >> 5;
    const int lane = t & 31;
    const int g    = lane & 7;          // granule (8 fp16 = 16B)
    const int rsub = lane >> 3;         // 0..3 row-in-warp

    ((float4*)enc_s)[t] = ((const float4*)(g_enc_proj + (size_t)bt * JD))[t];
    for (int i = t; i < JD; i += 256)
        wb_s[i] = Wout[(size_t)i * VO + (VO - 1)];
    __syncthreads();

    const float bias_bl = bout[VO - 1];

    #pragma unroll
    for (int p = 0; p < 4; p++) {
        const int u = p * 32 + warp * 4 + rsub;
        const float* prow = g_pred_proj + ((size_t)(b * U_ + u)) * JD;
        float accb = 0.f;
        #pragma unroll 4
        for (int c = 0; c < NCHUNK; c++) {
            const int j0 = c * KC + g * 8;
            float4 pa = *(const float4*)(prow + j0);
            float4 pb = *(const float4*)(prow + j0 + 4);
            float h0 = fmaxf(pa.x + enc_s[j0 + 0], 0.f);
            float h1 = fmaxf(pa.y + enc_s[j0 + 1], 0.f);
            float h2 = fmaxf(pa.z + enc_s[j0 + 2], 0.f);
            float h3 = fmaxf(pa.w + enc_s[j0 + 3], 0.f);
            float h4 = fmaxf(pb.x + enc_s[j0 + 4], 0.f);
            float h5 = fmaxf(pb.y + enc_s[j0 + 5], 0.f);
            float h6 = fmaxf(pb.z + enc_s[j0 + 6], 0.f);
            float h7 = fmaxf(pb.w + enc_s[j0 + 7], 0.f);
            accb += h0 * wb_s[j0 + 0] + h1 * wb_s[j0 + 1]
                  + h2 * wb_s[j0 + 2] + h3 * wb_s[j0 + 3]
                  + h4 * wb_s[j0 + 4] + h5 * wb_s[j0 + 5]
                  + h6 * wb_s[j0 + 6] + h7 * wb_s[j0 + 7];
            __half2 v0 = __floats2half2_rn(h0, h1);
            __half2 v1 = __floats2half2_rn(h2, h3);
            __half2 v2 = __floats2half2_rn(h4, h5);
            __half2 v3 = __floats2half2_rn(h6, h7);
            __half* dst = g_A16 + (((size_t)bt * NCHUNK + c) * U_ + u) * KC + g * 8;
            *(uint4*)dst = make_uint4(
                *(uint32_t*)&v0, *(uint32_t*)&v1, *(uint32_t*)&v2, *(uint32_t*)&v3);
        }
        // reduce over the 8 granule-lanes sharing row u
        accb += __shfl_xor_sync(0xffffffffu, accb, 1);
        accb += __shfl_xor_sync(0xffffffffu, accb, 2);
        accb += __shfl_xor_sync(0xffffffffu, accb, 4);
        if (g == 0)
            out[((size_t)bt * U_ + u) * VO + (VO - 1)] = accb + bias_bl;
    }
}

// =====================================================================
// kernel 4: fused joint GEMM (cols 0..1023): cp.async A16 + W16, mma f16
// =====================================================================
__global__ void __launch_bounds__(256, 2) joint_main(
    const float* __restrict__ bout, float* __restrict__ out)
{
    extern __shared__ char sm[];

    const int bt    = blockIdx.y;          // 0..1023
    const int ntile = blockIdx.x;          // 0..7
    const int n0    = ntile * 128;
    const int t     = threadIdx.x;
    const int warp  = t >> 5;
    const int lane  = t & 31;
    const int wm    = warp >> 2;           // 0..1 (M)
    const int wn    = warp & 3;            // 0..3 (N)
    const int lr    = lane & 15;
    const int lc    = (lane >> 4) * 8;

    const __half* Abase = g_A16 + (size_t)bt * NCHUNK * U_ * KC;

    auto issueAB = [&](int c, int buf) {
        // A: 128 rows x 64 fp16 (contiguous 16KB), 4 granules/thread
        const __half* asrc = Abase + (size_t)c * U_ * KC;
        __half* adst = (__half*)(sm + SM_A + buf * 18432);
        #pragma unroll
        for (int i = 0; i < 4; i++) {
            int flat = t + 256 * i;                 // 0..1023
            int row = flat >> 3, g = flat & 7;      // 128 rows x 8 x 16B
            cp16(adst + row * APITCH + g * 8, asrc + row * KC + g * 8);
        }
        // B: 64 k-rows x 128 n fp16
        const __half* bsrc = g_W16 + (size_t)(c * KC) * 1024 + n0;
        __half* bdst = (__half*)(sm + SM_B + buf * 17408);
        #pragma unroll
        for (int i = 0; i < 4; i++) {
            int flat = t + 256 * i;                 // 0..1023
            int row = flat >> 4, c16 = flat & 15;   // 64 rows x 16 x 16B
            cp16(bdst + row * BPITCH + c16 * 8, bsrc + (size_t)row * 1024 + c16 * 8);
        }
        cp_commit();
    };

    float acc[4][4][4] = {};

    issueAB(0, 0);

    for (int c = 0; c < NCHUNK; c++) {
        const int cur = c & 1, nxt = cur ^ 1;
        cp_wait_all();
        __syncthreads();
        if (c < NCHUNK - 1) issueAB(c + 1, nxt);

        uint32_t aB = smem_u32(sm + SM_A + cur * 18432) + (uint32_t)(((wm * 64 + lr) * APITCH + lc) * 2);
        uint32_t bB = smem_u32(sm + SM_B + cur * 17408) + (uint32_t)((lr * BPITCH + wn * 32 + lc) * 2);

        #pragma unroll
        for (int ks = 0; ks < 4; ks++) {
            uint32_t bq[2][4];
            #pragma unroll
            for (int n2 = 0; n2 < 2; n2++)
                ldm_x4_t(bq[n2], bB + (uint32_t)((ks * 16 * BPITCH + n2 * 16) * 2));
            #pragma unroll
            for (int mt = 0; mt < 4; mt++) {
                uint32_t a[4];
                ldm_x4(a, aB + (uint32_t)((mt * 16 * APITCH + ks * 16) * 2));
                #pragma unroll
                for (int nt = 0; nt < 4; nt++) {
                    const uint32_t* bp = &bq[nt >> 1][(nt & 1) * 2];
                    mma16816(acc[mt][nt], a, bp);
                }
            }
        }
        __syncthreads();   // all warps done reading cur before next overwrite cycle
    }

    // ---- coalesced epilogue: stage f32 tile in smem, then contiguous STG ----
    float* stg = (float*)sm;               // 128 x 132 floats = 67584 B
    const int gid = lane >> 2, tig = lane & 3;
    #pragma unroll
    for (int mt = 0; mt < 4; mt++) {
        #pragma unroll
        for (int nt = 0; nt < 4; nt++) {
            float* cv = acc[mt][nt];
            int u0 = wm * 64 + mt * 16 + gid;
            int c0 = wn * 32 + nt * 8 + tig * 2;
            *(float2*)&stg[u0 * 132 + c0]       = make_float2(cv[0], cv[1]);
            *(float2*)&stg[(u0 + 8) * 132 + c0] = make_float2(cv[2], cv[3]);
        }
    }
    __syncthreads();

    float bo[4];
    #pragma unroll
    for (int i = 0; i < 4; i++) bo[i] = bout[n0 + i * 32 + lane];

    #pragma unroll
    for (int ri = 0; ri < 16; ri++) {
        int row = warp * 16 + ri;
        float* orow = out + ((size_t)bt * U_ + row) * VO + n0;
        #pragma unroll
        for (int i = 0; i < 4; i++)
            orow[i * 32 + lane] = stg[row * 132 + i * 32 + lane] + bo[i];
    }
}

// =====================================================================
extern "C" void kernel_launch(void* const* d_in, const int* in_sizes, int n_in,
                              void* d_out, int out_size)
{
    (void)in_sizes; (void)n_in; (void)out_size;
    const float* enc    = (const float*)d_in[0];
    const float* pred   = (const float*)d_in[1];
    const float* W_enc  = (const float*)d_in[2];
    const float* b_enc  = (const float*)d_in[3];
    const float* W_pred = (const float*)d_in[4];
    const float* b_pred = (const float*)d_in[5];
    const float* W_out  = (const float*)d_in[6];
    const float* b_out  = (const float*)d_in[7];
    float* out = (float*)d_out;

    void *pe, *pp;
    cudaGetSymbolAddress(&pe, g_enc_proj);
    cudaGetSymbolAddress(&pp, g_pred_proj);
    float* genc  = (float*)pe;
    float* gpred = (float*)pp;

    cudaFuncSetAttribute(joint_main, cudaFuncAttributeMaxDynamicSharedMemorySize, SM_TOTAL);

    dim3 pg1(JD / 64, (B_ * T_) / 64);
    proj_gemm<<<pg1, 256>>>(enc, W_enc, b_enc, genc, B_ * T_, DE, JD);
    dim3 pg2(JD / 64, (B_ * U_) / 64);
    proj_gemm<<<pg2, 256>>>(pred, W_pred, b_pred, gpred, B_ * U_, DP, JD);
    prep_w<<<(JD * 1024 + 255) / 256, 256>>>(W_out);
    precompute_A<<<B_ * T_, 256>>>(W_out, b_out, out);

    dim3 grid(8, B_ * T_);               // 8 n-tiles x 1024 (b,t) tiles
    joint_main<<<grid, 256, SM_TOTAL>>>(b_out, out);
}

// round 8
// speedup vs baseline: 3.5901x; 1.0326x over previous
#include <cuda_runtime.h>
#include <cuda_fp16.h>
#include <stdint.h>

#define B_   4
#define T_   256
#define U_   128
#define DE   512
#define DP   640
#define JD   1024
#define VO   1025

#define KC     64
#define NCHUNK 16
#define APITCH 72    // 64 + 8 pad (fp16 elems), pitch 144B
#define BPITCH 136   // 128 + 8 pad, pitch 272B

// ---- dynamic smem layout (bytes): 3-stage pipeline ----
#define A_SZ   18432                     // half[128][72]
#define B_SZ   17408                     // half[64][136]
#define SM_A   0                         // 3 x A_SZ
#define SM_B   (3*A_SZ)                  // 3 x B_SZ
#define SM_TOTAL (SM_B + 3*B_SZ)         // 107520 bytes -> 2 CTAs/SM
// epilogue staging reuses [0, 128*132*4 = 67584) ✓

// ---- device scratch ----
__device__ __align__(16) float g_enc_proj[B_*T_*JD];      // 4 MB
__device__ __align__(16) float g_pred_proj[B_*U_*JD];     // 2 MB
__device__ __align__(16) __half g_W16[JD*1024];           // [k][n] 2 MB
__device__ __align__(16) __half g_A16[(size_t)B_*T_*NCHUNK*U_*KC];  // 256 MB

// =====================================================================
// helpers
// =====================================================================
__device__ __forceinline__ uint32_t smem_u32(const void* p) {
    return (uint32_t)__cvta_generic_to_shared(p);
}
__device__ __forceinline__ void ldm_x4(uint32_t* r, uint32_t addr) {
    asm volatile("ldmatrix.sync.aligned.m8n8.x4.shared.b16 {%0,%1,%2,%3}, [%4];"
                 : "=r"(r[0]), "=r"(r[1]), "=r"(r[2]), "=r"(r[3]) : "r"(addr));
}
__device__ __forceinline__ void ldm_x4_t(uint32_t* r, uint32_t addr) {
    asm volatile("ldmatrix.sync.aligned.m8n8.x4.trans.shared.b16 {%0,%1,%2,%3}, [%4];"
                 : "=r"(r[0]), "=r"(r[1]), "=r"(r[2]), "=r"(r[3]) : "r"(addr));
}
__device__ __forceinline__ void mma16816(float* c, const uint32_t* a, const uint32_t* b) {
    asm volatile(
        "mma.sync.aligned.m16n8k16.row.col.f32.f16.f16.f32 "
        "{%0,%1,%2,%3},{%4,%5,%6,%7},{%8,%9},{%0,%1,%2,%3};"
        : "+f"(c[0]), "+f"(c[1]), "+f"(c[2]), "+f"(c[3])
        : "r"(a[0]), "r"(a[1]), "r"(a[2]), "r"(a[3]), "r"(b[0]), "r"(b[1]));
}
__device__ __forceinline__ void cp16(void* dst_smem, const void* src) {
    uint32_t d = smem_u32(dst_smem);
    asm volatile("cp.async.cg.shared.global [%0], [%1], 16;\n" :: "r"(d), "l"(src) : "memory");
}
__device__ __forceinline__ void cp_commit() {
    asm volatile("cp.async.commit_group;\n" ::: "memory");
}
template <int N>
__device__ __forceinline__ void cp_wait() {
    asm volatile("cp.async.wait_group %0;\n" :: "n"(N) : "memory");
}

// =====================================================================
// kernel 1: fp32 projection GEMM  C[M,J] = A[M,K] @ W[K,J] + bias
// =====================================================================
__global__ void __launch_bounds__(256) proj_gemm(
    const float* __restrict__ A, const float* __restrict__ W,
    const float* __restrict__ bias, float* __restrict__ C,
    int M, int K, int J)
{
    __shared__ float As[16][68];
    __shared__ float Bs[16][64];
    const int tx = threadIdx.x & 15;
    const int ty = threadIdx.x >> 4;
    const int m0 = blockIdx.y * 64;
    const int n0 = blockIdx.x * 64;

    float acc[4][4] = {};

    for (int k0 = 0; k0 < K; k0 += 16) {
        {
            int t = threadIdx.x;
            int m  = t >> 2, k4 = (t & 3) * 4;
            float4 a = *(const float4*)(A + (size_t)(m0 + m) * K + k0 + k4);
            As[k4 + 0][m] = a.x; As[k4 + 1][m] = a.y;
            As[k4 + 2][m] = a.z; As[k4 + 3][m] = a.w;
            int kk = t >> 4, n4 = (t & 15) * 4;
            *(float4*)&Bs[kk][n4] = *(const float4*)(W + (size_t)(k0 + kk) * J + n0 + n4);
        }
        __syncthreads();
        #pragma unroll
        for (int k = 0; k < 16; k++) {
            float a[4], b[4];
            *(float4*)a = *(float4*)&As[k][ty * 4];
            *(float4*)b = *(float4*)&Bs[k][tx * 4];
            #pragma unroll
            for (int i = 0; i < 4; i++)
                #pragma unroll
                for (int j = 0; j < 4; j++)
                    acc[i][j] += a[i] * b[j];
        }
        __syncthreads();
    }
    #pragma unroll
    for (int i = 0; i < 4; i++) {
        int m = m0 + ty * 4 + i;
        #pragma unroll
        for (int j = 0; j < 4; j++) {
            int n = n0 + tx * 4 + j;
            C[(size_t)m * J + n] = acc[i][j] + bias[n];
        }
    }
}

// =====================================================================
// kernel 2: W_out[:, 0:1024] -> fp16 [k][n]
// =====================================================================
__global__ void prep_w(const float* __restrict__ W) {
    int idx = blockIdx.x * 256 + threadIdx.x;
    if (idx >= JD * 1024) return;
    int j = idx >> 10, n = idx & 1023;
    g_W16[idx] = __float2half_rn(W[(size_t)j * VO + n]);
}

// =====================================================================
// kernel 3: precompute fp16 joint activations + blank column
// chunk-outer loop; enc/wb hoisted to registers (1x LDS instead of 4x)
// =====================================================================
__global__ void __launch_bounds__(256) precompute_A(
    const float* __restrict__ Wout, const float* __restrict__ bout,
    float* __restrict__ out)
{
    __shared__ float enc_s[JD];
    __shared__ float wb_s[JD];
    const int bt   = blockIdx.x;
    const int b    = bt >> 8;
    const int t    = threadIdx.x;
    const int warp = t >> 5;
    const int lane = t & 31;
    const int g    = lane & 7;          // granule (8 fp16 = 16B)
    const int rsub = lane >> 3;         // 0..3 row-in-warp
    const int u0   = warp * 4 + rsub;   // + p*32

    ((float4*)enc_s)[t] = ((const float4*)(g_enc_proj + (size_t)bt * JD))[t];
    for (int i = t; i < JD; i += 256)
        wb_s[i] = Wout[(size_t)i * VO + (VO - 1)];
    __syncthreads();

    const float* pbase = g_pred_proj + ((size_t)(b * U_ + u0)) * JD;
    float accb[4] = {0.f, 0.f, 0.f, 0.f};

    #pragma unroll 2
    for (int c = 0; c < NCHUNK; c++) {
        const int j0 = c * KC + g * 8;
        float4 e0 = *(const float4*)(enc_s + j0);
        float4 e1 = *(const float4*)(enc_s + j0 + 4);
        float4 w0 = *(const float4*)(wb_s + j0);
        float4 w1 = *(const float4*)(wb_s + j0 + 4);
        __half* dstc = g_A16 + (((size_t)bt * NCHUNK + c) * U_ + u0) * KC + g * 8;
        #pragma unroll
        for (int p = 0; p < 4; p++) {
            const float* prow = pbase + (size_t)(p * 32) * JD + j0;
            float4 pa = *(const float4*)(prow);
            float4 pb = *(const float4*)(prow + 4);
            float h0 = fmaxf(pa.x + e0.x, 0.f);
            float h1 = fmaxf(pa.y + e0.y, 0.f);
            float h2 = fmaxf(pa.z + e0.z, 0.f);
            float h3 = fmaxf(pa.w + e0.w, 0.f);
            float h4 = fmaxf(pb.x + e1.x, 0.f);
            float h5 = fmaxf(pb.y + e1.y, 0.f);
            float h6 = fmaxf(pb.z + e1.z, 0.f);
            float h7 = fmaxf(pb.w + e1.w, 0.f);
            accb[p] += h0 * w0.x + h1 * w0.y + h2 * w0.z + h3 * w0.w
                     + h4 * w1.x + h5 * w1.y + h6 * w1.z + h7 * w1.w;
            __half2 v0 = __floats2half2_rn(h0, h1);
            __half2 v1 = __floats2half2_rn(h2, h3);
            __half2 v2 = __floats2half2_rn(h4, h5);
            __half2 v3 = __floats2half2_rn(h6, h7);
            *(uint4*)(dstc + (size_t)(p * 32) * KC) = make_uint4(
                *(uint32_t*)&v0, *(uint32_t*)&v1, *(uint32_t*)&v2, *(uint32_t*)&v3);
        }
    }

    const float bias_bl = bout[VO - 1];
    #pragma unroll
    for (int p = 0; p < 4; p++) {
        float a = accb[p];
        a += __shfl_xor_sync(0xffffffffu, a, 1);
        a += __shfl_xor_sync(0xffffffffu, a, 2);
        a += __shfl_xor_sync(0xffffffffu, a, 4);
        if (g == 0)
            out[((size_t)bt * U_ + u0 + p * 32) * VO + (VO - 1)] = a + bias_bl;
    }
}

// =====================================================================
// kernel 4: fused joint GEMM (cols 0..1023): 3-stage cp.async + mma f16
// =====================================================================
__global__ void __launch_bounds__(256, 2) joint_main(
    const float* __restrict__ bout, float* __restrict__ out)
{
    extern __shared__ char sm[];

    const int bt    = blockIdx.y;          // 0..1023
    const int ntile = blockIdx.x;          // 0..7
    const int n0    = ntile * 128;
    const int t     = threadIdx.x;
    const int warp  = t >> 5;
    const int lane  = t & 31;
    const int wm    = warp >> 2;           // 0..1 (M)
    const int wn    = warp & 3;            // 0..3 (N)
    const int lr    = lane & 15;
    const int lc    = (lane >> 4) * 8;

    const __half* Abase = g_A16 + (size_t)bt * NCHUNK * U_ * KC;

    auto issueAB = [&](int c, int buf) {
        const __half* asrc = Abase + (size_t)c * U_ * KC;
        __half* adst = (__half*)(sm + SM_A + buf * A_SZ);
        #pragma unroll
        for (int i = 0; i < 4; i++) {
            int flat = t + 256 * i;                 // 0..1023
            int row = flat >> 3, g = flat & 7;      // 128 rows x 8 x 16B
            cp16(adst + row * APITCH + g * 8, asrc + row * KC + g * 8);
        }
        const __half* bsrc = g_W16 + (size_t)(c * KC) * 1024 + n0;
        __half* bdst = (__half*)(sm + SM_B + buf * B_SZ);
        #pragma unroll
        for (int i = 0; i < 4; i++) {
            int flat = t + 256 * i;                 // 0..1023
            int row = flat >> 4, c16 = flat & 15;   // 64 rows x 16 x 16B
            cp16(bdst + row * BPITCH + c16 * 8, bsrc + (size_t)row * 1024 + c16 * 8);
        }
        cp_commit();
    };

    float acc[4][4][4] = {};

    issueAB(0, 0);
    issueAB(1, 1);

    int buf = 0;
    for (int c = 0; c < NCHUNK; c++) {
        cp_wait<1>();        // group for chunk c complete (c+1 may be in flight)
        __syncthreads();     // all warps: c's data visible AND done reading buf of c-1
        if (c + 2 < NCHUNK) {
            int nb = buf + 2; if (nb >= 3) nb -= 3;
            issueAB(c + 2, nb);
        }

        uint32_t aB = smem_u32(sm + SM_A + buf * A_SZ) + (uint32_t)(((wm * 64 + lr) * APITCH + lc) * 2);
        uint32_t bB = smem_u32(sm + SM_B + buf * B_SZ) + (uint32_t)((lr * BPITCH + wn * 32 + lc) * 2);

        #pragma unroll
        for (int ks = 0; ks < 4; ks++) {
            uint32_t bq[2][4];
            #pragma unroll
            for (int n2 = 0; n2 < 2; n2++)
                ldm_x4_t(bq[n2], bB + (uint32_t)((ks * 16 * BPITCH + n2 * 16) * 2));
            #pragma unroll
            for (int mt = 0; mt < 4; mt++) {
                uint32_t a[4];
                ldm_x4(a, aB + (uint32_t)((mt * 16 * APITCH + ks * 16) * 2));
                #pragma unroll
                for (int nt = 0; nt < 4; nt++) {
                    const uint32_t* bp = &bq[nt >> 1][(nt & 1) * 2];
                    mma16816(acc[mt][nt], a, bp);
                }
            }
        }
        if (++buf >= 3) buf = 0;
    }
    __syncthreads();   // protect staging region (aliases buffers)

    // ---- coalesced epilogue: stage f32 tile in smem, then contiguous STG ----
    float* stg = (float*)sm;               // 128 x 132 floats = 67584 B
    const int gid = lane >> 2, tig = lane & 3;
    #pragma unroll
    for (int mt = 0; mt < 4; mt++) {
        #pragma unroll
        for (int nt = 0; nt < 4; nt++) {
            float* cv = acc[mt][nt];
            int u0 = wm * 64 + mt * 16 + gid;
            int c0 = wn * 32 + nt * 8 + tig * 2;
            *(float2*)&stg[u0 * 132 + c0]       = make_float2(cv[0], cv[1]);
            *(float2*)&stg[(u0 + 8) * 132 + c0] = make_float2(cv[2], cv[3]);
        }
    }
    __syncthreads();

    float bo[4];
    #pragma unroll
    for (int i = 0; i < 4; i++) bo[i] = bout[n0 + i * 32 + lane];

    #pragma unroll
    for (int ri = 0; ri < 16; ri++) {
        int row = warp * 16 + ri;
        float* orow = out + ((size_t)bt * U_ + row) * VO + n0;
        #pragma unroll
        for (int i = 0; i < 4; i++)
            orow[i * 32 + lane] = stg[row * 132 + i * 32 + lane] + bo[i];
    }
}

// =====================================================================
extern "C" void kernel_launch(void* const* d_in, const int* in_sizes, int n_in,
                              void* d_out, int out_size)
{
    (void)in_sizes; (void)n_in; (void)out_size;
    const float* enc    = (const float*)d_in[0];
    const float* pred   = (const float*)d_in[1];
    const float* W_enc  = (const float*)d_in[2];
    const float* b_enc  = (const float*)d_in[3];
    const float* W_pred = (const float*)d_in[4];
    const float* b_pred = (const float*)d_in[5];
    const float* W_out  = (const float*)d_in[6];
    const float* b_out  = (const float*)d_in[7];
    float* out = (float*)d_out;

    void *pe, *pp;
    cudaGetSymbolAddress(&pe, g_enc_proj);
    cudaGetSymbolAddress(&pp, g_pred_proj);
    float* genc  = (float*)pe;
    float* gpred = (float*)pp;

    cudaFuncSetAttribute(joint_main, cudaFuncAttributeMaxDynamicSharedMemorySize, SM_TOTAL);

    dim3 pg1(JD / 64, (B_ * T_) / 64);
    proj_gemm<<<pg1, 256>>>(enc, W_enc, b_enc, genc, B_ * T_, DE, JD);
    dim3 pg2(JD / 64, (B_ * U_) / 64);
    proj_gemm<<<pg2, 256>>>(pred, W_pred, b_pred, gpred, B_ * U_, DP, JD);
    prep_w<<<(JD * 1024 + 255) / 256, 256>>>(W_out);
    precompute_A<<<B_ * T_, 256>>>(W_out, b_out, out);

    dim3 grid(8, B_ * T_);               // 8 n-tiles x 1024 (b,t) tiles
    joint_main<<<grid, 256, SM_TOTAL>>>(b_out, out);
}